// round 4
// baseline (speedup 1.0000x reference)
#include <cuda_runtime.h>
#include <math.h>

// Problem constants
#define Bb 4
#define Tt 1024
#define Cc 1024
#define Hh 16
#define HSs 64
#define Ll 12
#define Vv 50304
#define Mm (Bb*Tt)      // 4096
#define FFd (4*Cc)      // 4096

// ---------------- scratch (static device memory; no allocations) ----------------
__device__ float g_x[(size_t)Mm*Cc];
__device__ float g_h[(size_t)Mm*Cc];
__device__ float g_q[(size_t)Mm*Cc];
__device__ float g_k[(size_t)Mm*Cc];
__device__ float g_v[(size_t)Mm*Cc];
__device__ float g_att[(size_t)Mm*Cc];
__device__ float g_ffh[(size_t)Mm*FFd];
__device__ float g_wei[(size_t)Bb*Hh*Tt*Tt];   // 268 MB attention scores
__device__ float g_rowloss[Mm];

// ---------------- helpers ----------------
__device__ __forceinline__ float block_reduce(float v, float* buf, bool ismax) {
    int tid = threadIdx.x;            // blockDim.x == 256
    buf[tid] = v;
    __syncthreads();
    #pragma unroll
    for (int s = 128; s > 0; s >>= 1) {
        if (tid < s) buf[tid] = ismax ? fmaxf(buf[tid], buf[tid + s]) : (buf[tid] + buf[tid + s]);
        __syncthreads();
    }
    float r = buf[0];
    __syncthreads();
    return r;
}

// ---------------- embed: x = tok_emb[idx] + pos_emb ----------------
__global__ void embed_k(const int* __restrict__ idx, const float* __restrict__ tok,
                        const float* __restrict__ pos, float* __restrict__ x) {
    int i4 = blockIdx.x * blockDim.x + threadIdx.x;   // over Mm*Cc/4
    if (i4 >= Mm * Cc / 4) return;
    int c  = (i4 % (Cc / 4)) * 4;
    int bt = i4 / (Cc / 4);
    int t  = bt % Tt;
    int tk = idx[bt];
    float4 a = *(const float4*)&tok[(size_t)tk * Cc + c];
    float4 p = *(const float4*)&pos[(size_t)t * Cc + c];
    a.x += p.x; a.y += p.y; a.z += p.z; a.w += p.w;
    *(float4*)&x[(size_t)bt * Cc + c] = a;
}

// ---------------- layernorm: one block (256 thr) per row of C=1024 ----------------
__global__ void layernorm_k(const float* __restrict__ x, const float* __restrict__ g,
                            const float* __restrict__ b, float* __restrict__ y) {
    __shared__ float buf[256];
    int tid = threadIdx.x;
    const float* xr = x + (size_t)blockIdx.x * Cc;
    float*       yr = y + (size_t)blockIdx.x * Cc;
    float4 v = ((const float4*)xr)[tid];
    float s  = v.x + v.y + v.z + v.w;
    float sq = v.x*v.x + v.y*v.y + v.z*v.z + v.w*v.w;
    s  = block_reduce(s,  buf, false);
    sq = block_reduce(sq, buf, false);
    float mean = s * (1.0f / Cc);
    float var  = sq * (1.0f / Cc) - mean * mean;
    float r    = rsqrtf(var + 1e-5f);
    float4 gg = ((const float4*)g)[tid];
    float4 bb = ((const float4*)b)[tid];
    v.x = (v.x - mean) * r * gg.x + bb.x;
    v.y = (v.y - mean) * r * gg.y + bb.y;
    v.z = (v.z - mean) * r * gg.z + bb.z;
    v.w = (v.w - mean) * r * gg.w + bb.w;
    ((float4*)yr)[tid] = v;
}

// ---------------- generic fp32 GEMM: C = op(A@B + bias + res) ----------------
// 128x128 tile, BK=16, 256 threads, 8x8 per-thread micro-tile.
// All shapes used are divisible (M%128==0, N%128==0, K%16==0): no bounds checks.
template<bool BIAS, bool RES, bool RELU>
__global__ void __launch_bounds__(256) sgemm_k(
    int M, int N, int K,
    const float* __restrict__ A, int lda,
    const float* __restrict__ Bm, int ldb,
    const float* __restrict__ bias,
    const float* __restrict__ res, int ldr,
    float* __restrict__ C, int ldc)
{
    __shared__ float As[128][16];
    __shared__ float Bs[16][128];
    const int tid = threadIdx.x;
    const int rowBase = blockIdx.y * 128;
    const int colBase = blockIdx.x * 128;
    const int tx = tid & 15, ty = tid >> 4;
    float acc[8][8] = {};

    for (int k0 = 0; k0 < K; k0 += 16) {
        #pragma unroll
        for (int p = 0; p < 2; ++p) {
            int idx = tid + 256 * p;
            int r  = idx >> 2;            // 0..127
            int c4 = (idx & 3) * 4;       // 0,4,8,12
            float4 va = *(const float4*)&A[(size_t)(rowBase + r) * lda + k0 + c4];
            *(float4*)&As[r][c4] = va;
            int rb  = idx >> 5;           // 0..15
            int cb4 = (idx & 31) * 4;     // 0..124
            float4 vb = *(const float4*)&Bm[(size_t)(k0 + rb) * ldb + colBase + cb4];
            *(float4*)&Bs[rb][cb4] = vb;
        }
        __syncthreads();
        #pragma unroll
        for (int k = 0; k < 16; ++k) {
            float a[8], bb[8];
            #pragma unroll
            for (int i = 0; i < 8; ++i) a[i] = As[ty * 8 + i][k];
            float4 b0 = *(const float4*)&Bs[k][tx * 8];
            float4 b1 = *(const float4*)&Bs[k][tx * 8 + 4];
            bb[0]=b0.x; bb[1]=b0.y; bb[2]=b0.z; bb[3]=b0.w;
            bb[4]=b1.x; bb[5]=b1.y; bb[6]=b1.z; bb[7]=b1.w;
            #pragma unroll
            for (int i = 0; i < 8; ++i)
                #pragma unroll
                for (int j = 0; j < 8; ++j)
                    acc[i][j] += a[i] * bb[j];
        }
        __syncthreads();
    }

    #pragma unroll
    for (int i = 0; i < 8; ++i) {
        int row = rowBase + ty * 8 + i;
        #pragma unroll
        for (int j = 0; j < 8; j += 4) {
            int col = colBase + tx * 8 + j;
            float4 o;
            o.x = acc[i][j];   o.y = acc[i][j+1]; o.z = acc[i][j+2]; o.w = acc[i][j+3];
            if (BIAS) {
                float4 bv = *(const float4*)&bias[col];
                o.x += bv.x; o.y += bv.y; o.z += bv.z; o.w += bv.w;
            }
            if (RES) {
                float4 rv = *(const float4*)&res[(size_t)row * ldr + col];
                o.x += rv.x; o.y += rv.y; o.z += rv.z; o.w += rv.w;
            }
            if (RELU) {
                o.x = fmaxf(o.x, 0.f); o.y = fmaxf(o.y, 0.f);
                o.z = fmaxf(o.z, 0.f); o.w = fmaxf(o.w, 0.f);
            }
            *(float4*)&C[(size_t)row * ldc + col] = o;
        }
    }
}

// ---------------- attention scores: S = scale * Q K^T, causal mask ----------------
// grid (T/64, T/64, B*H), 256 threads; 64x64 tile, K=HS=64.
__global__ void __launch_bounds__(256) attn_scores_k(
    const float* __restrict__ q, const float* __restrict__ k, float* __restrict__ wei)
{
    int bh   = blockIdx.z;
    int b    = bh / Hh, h = bh % Hh;
    int row0 = blockIdx.y * 64, col0 = blockIdx.x * 64;
    float* W = wei + (size_t)bh * Tt * Tt;
    int tid = threadIdx.x;

    if (col0 > row0 + 63) {     // fully masked tile: write -inf, no compute
        #pragma unroll
        for (int p = 0; p < 4; ++p) {
            int idx = tid + 256 * p;
            int r = idx >> 4, c4 = (idx & 15) * 4;
            float4 ninf = make_float4(-INFINITY, -INFINITY, -INFINITY, -INFINITY);
            *(float4*)&W[(size_t)(row0 + r) * Tt + col0 + c4] = ninf;
        }
        return;
    }

    __shared__ float Qs[64][64];     // [m][d]
    __shared__ float KsT[64][64];    // [d][s]  (transposed for conflict-free reads)
    const float* Qb = q + (size_t)b * Tt * Cc + h * HSs;
    const float* Kb = k + (size_t)b * Tt * Cc + h * HSs;

    #pragma unroll
    for (int p = 0; p < 4; ++p) {
        int idx = tid + 256 * p;
        int r = idx >> 4, c4 = (idx & 15) * 4;
        float4 vq = *(const float4*)&Qb[(size_t)(row0 + r) * Cc + c4];
        *(float4*)&Qs[r][c4] = vq;
        float4 vk = *(const float4*)&Kb[(size_t)(col0 + r) * Cc + c4];
        KsT[c4 + 0][r] = vk.x; KsT[c4 + 1][r] = vk.y;
        KsT[c4 + 2][r] = vk.z; KsT[c4 + 3][r] = vk.w;
    }
    __syncthreads();

    int tx = tid & 15, ty = tid >> 4;
    float acc[4][4] = {};
    #pragma unroll 8
    for (int d = 0; d < 64; ++d) {
        float a[4];
        #pragma unroll
        for (int i = 0; i < 4; ++i) a[i] = Qs[ty * 4 + i][d];
        float4 bv = *(const float4*)&KsT[d][tx * 4];
        #pragma unroll
        for (int i = 0; i < 4; ++i) {
            acc[i][0] += a[i] * bv.x; acc[i][1] += a[i] * bv.y;
            acc[i][2] += a[i] * bv.z; acc[i][3] += a[i] * bv.w;
        }
    }

    const float scale = 0.125f;  // HS^-0.5 = 1/8
    #pragma unroll
    for (int i = 0; i < 4; ++i) {
        int r = row0 + ty * 4 + i;
        int c = col0 + tx * 4;
        float4 o;
        o.x = (c + 0 <= r) ? acc[i][0] * scale : -INFINITY;
        o.y = (c + 1 <= r) ? acc[i][1] * scale : -INFINITY;
        o.z = (c + 2 <= r) ? acc[i][2] * scale : -INFINITY;
        o.w = (c + 3 <= r) ? acc[i][3] * scale : -INFINITY;
        *(float4*)&W[(size_t)r * Tt + c] = o;
    }
}

// ---------------- row softmax over T=1024 (in place) ----------------
__global__ void softmax_rows_k(float* __restrict__ wei) {
    __shared__ float buf[256];
    float* W = wei + (size_t)blockIdx.x * Tt;
    int tid = threadIdx.x;
    float4 v = ((const float4*)W)[tid];
    float m = fmaxf(fmaxf(v.x, v.y), fmaxf(v.z, v.w));
    m = block_reduce(m, buf, true);
    float4 e;
    e.x = expf(v.x - m); e.y = expf(v.y - m);
    e.z = expf(v.z - m); e.w = expf(v.w - m);
    float s = e.x + e.y + e.z + e.w;
    s = block_reduce(s, buf, false);
    float inv = 1.0f / s;
    e.x *= inv; e.y *= inv; e.z *= inv; e.w *= inv;
    ((float4*)W)[tid] = e;
}

// ---------------- AV: out = softmax(S) @ V   (skips causally-zero K tiles) ----------------
// grid (T/64, B*H), 256 threads; 64x64 tile (N = HS = 64), BK=32.
__global__ void __launch_bounds__(256) attn_av_k(
    const float* __restrict__ wei, const float* __restrict__ v, float* __restrict__ out)
{
    int bh = blockIdx.y;
    int b  = bh / Hh, h = bh % Hh;
    int row0 = blockIdx.x * 64;
    const float* Wb = wei + (size_t)bh * Tt * Tt;
    const float* Vb = v   + (size_t)b * Tt * Cc + h * HSs;
    float*       Ob = out + (size_t)b * Tt * Cc + h * HSs;

    __shared__ float Ws[64][36];   // [m][k], padded
    __shared__ float Vs[32][64];   // [k][n]
    int tid = threadIdx.x;
    int tx = tid & 15, ty = tid >> 4;
    float acc[4][4] = {};

    int kmax = row0 + 64;          // weights are 0 beyond the diagonal block
    for (int k0 = 0; k0 < kmax; k0 += 32) {
        #pragma unroll
        for (int p = 0; p < 2; ++p) {
            int idx = tid + 256 * p;
            int r  = idx >> 3;            // 0..63
            int c4 = (idx & 7) * 4;       // 0..28
            float4 vw = *(const float4*)&Wb[(size_t)(row0 + r) * Tt + k0 + c4];
            *(float4*)&Ws[r][c4] = vw;
            int rv  = idx >> 4;           // 0..31
            int cv4 = (idx & 15) * 4;     // 0..60
            float4 vv = *(const float4*)&Vb[(size_t)(k0 + rv) * Cc + cv4];
            *(float4*)&Vs[rv][cv4] = vv;
        }
        __syncthreads();
        #pragma unroll 8
        for (int k = 0; k < 32; ++k) {
            float a[4];
            #pragma unroll
            for (int i = 0; i < 4; ++i) a[i] = Ws[ty * 4 + i][k];
            float4 bv = *(const float4*)&Vs[k][tx * 4];
            #pragma unroll
            for (int i = 0; i < 4; ++i) {
                acc[i][0] += a[i] * bv.x; acc[i][1] += a[i] * bv.y;
                acc[i][2] += a[i] * bv.z; acc[i][3] += a[i] * bv.w;
            }
        }
        __syncthreads();
    }

    #pragma unroll
    for (int i = 0; i < 4; ++i) {
        float4 o; o.x = acc[i][0]; o.y = acc[i][1]; o.z = acc[i][2]; o.w = acc[i][3];
        *(float4*)&Ob[(size_t)(row0 + ty * 4 + i) * Cc + tx * 4] = o;
    }
}

// ---------------- loss: per-row logsumexp, then deterministic mean ----------------
__global__ void loss_rows_k(const float* __restrict__ logits, const int* __restrict__ targets,
                            float* __restrict__ rowloss) {
    __shared__ float buf[256];
    const float* L = logits + (size_t)blockIdx.x * Vv;
    int tid = threadIdx.x;
    const int V4 = Vv / 4;     // 12576
    float m = -INFINITY;
    for (int j = tid; j < V4; j += 256) {
        float4 v = ((const float4*)L)[j];
        m = fmaxf(m, fmaxf(fmaxf(v.x, v.y), fmaxf(v.z, v.w)));
    }
    m = block_reduce(m, buf, true);
    float s = 0.f;
    for (int j = tid; j < V4; j += 256) {
        float4 v = ((const float4*)L)[j];
        s += expf(v.x - m) + expf(v.y - m) + expf(v.z - m) + expf(v.w - m);
    }
    s = block_reduce(s, buf, false);
    if (tid == 0) rowloss[blockIdx.x] = logf(s) + m - L[targets[blockIdx.x]];
}

__global__ void loss_reduce_k(const float* __restrict__ rowloss, float* __restrict__ out) {
    __shared__ float buf[256];
    int tid = threadIdx.x;
    float s = 0.f;
    for (int j = tid; j < Mm; j += 256) s += rowloss[j];
    s = block_reduce(s, buf, false);
    if (tid == 0) out[0] = s / (float)Mm;
}

// ---------------- launch ----------------
extern "C" void kernel_launch(void* const* d_in, const int* in_sizes, int n_in,
                              void* d_out, int out_size)
{
    const int*   idx     = (const int*)d_in[0];
    const int*   targets = (const int*)d_in[1];
    const float* tok_emb = (const float*)d_in[2];
    const float* pos_emb = (const float*)d_in[3];
    const float* ln1_g   = (const float*)d_in[4];
    const float* ln1_b   = (const float*)d_in[5];
    const float* Wq      = (const float*)d_in[6];
    const float* Wk      = (const float*)d_in[7];
    const float* Wv      = (const float*)d_in[8];
    const float* Wo      = (const float*)d_in[9];
    const float* bo      = (const float*)d_in[10];
    const float* ln2_g   = (const float*)d_in[11];
    const float* ln2_b   = (const float*)d_in[12];
    const float* W1      = (const float*)d_in[13];
    const float* b1      = (const float*)d_in[14];
    const float* W2      = (const float*)d_in[15];
    const float* b2      = (const float*)d_in[16];
    const float* lnf_g   = (const float*)d_in[17];
    const float* lnf_b   = (const float*)d_in[18];
    const float* Wlm     = (const float*)d_in[19];
    const float* blm     = (const float*)d_in[20];
    float* out = (float*)d_out;

    float *px, *ph, *pq, *pk, *pv, *patt, *pffh, *pwei, *prl;
    cudaGetSymbolAddress((void**)&px,   g_x);
    cudaGetSymbolAddress((void**)&ph,   g_h);
    cudaGetSymbolAddress((void**)&pq,   g_q);
    cudaGetSymbolAddress((void**)&pk,   g_k);
    cudaGetSymbolAddress((void**)&pv,   g_v);
    cudaGetSymbolAddress((void**)&patt, g_att);
    cudaGetSymbolAddress((void**)&pffh, g_ffh);
    cudaGetSymbolAddress((void**)&pwei, g_wei);
    cudaGetSymbolAddress((void**)&prl,  g_rowloss);

    // embed
    embed_k<<<(Mm * Cc / 4 + 255) / 256, 256>>>(idx, tok_emb, pos_emb, px);

    dim3 gC(Cc / 128, Mm / 128);       // N=1024 GEMMs
    dim3 gF(FFd / 128, Mm / 128);      // N=4096 GEMM
    dim3 gS(Tt / 64, Tt / 64, Bb * Hh);
    dim3 gA(Tt / 64, Bb * Hh);

    for (int l = 0; l < Ll; ++l) {
        const size_t oCC = (size_t)l * Cc * Cc;
        const size_t oC  = (size_t)l * Cc;
        const size_t oCF = (size_t)l * Cc * FFd;
        const size_t oF  = (size_t)l * FFd;

        layernorm_k<<<Mm, 256>>>(px, ln1_g + oC, ln1_b + oC, ph);
        sgemm_k<false,false,false><<<gC, 256>>>(Mm, Cc, Cc, ph, Cc, Wq + oCC, Cc,
                                                nullptr, nullptr, 0, pq, Cc);
        sgemm_k<false,false,false><<<gC, 256>>>(Mm, Cc, Cc, ph, Cc, Wk + oCC, Cc,
                                                nullptr, nullptr, 0, pk, Cc);
        sgemm_k<false,false,false><<<gC, 256>>>(Mm, Cc, Cc, ph, Cc, Wv + oCC, Cc,
                                                nullptr, nullptr, 0, pv, Cc);
        attn_scores_k<<<gS, 256>>>(pq, pk, pwei);
        softmax_rows_k<<<Bb * Hh * Tt, 256>>>(pwei);
        attn_av_k<<<gA, 256>>>(pwei, pv, patt);
        sgemm_k<true,true,false><<<gC, 256>>>(Mm, Cc, Cc, patt, Cc, Wo + oCC, Cc,
                                              bo + oC, px, Cc, px, Cc);
        layernorm_k<<<Mm, 256>>>(px, ln2_g + oC, ln2_b + oC, ph);
        sgemm_k<true,false,true><<<gF, 256>>>(Mm, FFd, Cc, ph, Cc, W1 + oCF, FFd,
                                              b1 + oF, nullptr, 0, pffh, FFd);
        sgemm_k<true,true,false><<<gC, 256>>>(Mm, Cc, FFd, pffh, FFd, W2 + oCF, Cc,
                                              b2 + oC, px, Cc, px, Cc);
    }

    // final LN + LM head -> logits directly into d_out
    layernorm_k<<<Mm, 256>>>(px, lnf_g, lnf_b, ph);
    dim3 gV(Vv / 128, Mm / 128);       // 393 x 32
    sgemm_k<true,false,false><<<gV, 256>>>(Mm, Vv, Cc, ph, Cc, Wlm, Vv,
                                           blm, nullptr, 0, out, Vv);

    // loss (if the output buffer has room for it after the logits)
    long long logitsN = (long long)Mm * Vv;
    if ((long long)out_size > logitsN) {
        loss_rows_k<<<Mm, 256>>>(out, targets, prl);
        loss_reduce_k<<<1, 256>>>(prl, out + logitsN);
    }
}

// round 6
// speedup vs baseline: 1.9599x; 1.9599x over previous
#include <cuda_runtime.h>
#include <cuda_bf16.h>
#include <math.h>
#include <stdint.h>

// Problem constants
#define Bb 4
#define Tt 1024
#define Cc 1024
#define Hh 16
#define HSs 64
#define Ll 12
#define Vv 50304
#define Mm (Bb*Tt)      // 4096
#define FFd (4*Cc)      // 4096

// ---------------- scratch (static device memory; no allocations) ----------------
__device__ float g_x[(size_t)Mm*Cc];
__device__ float g_h[(size_t)Mm*Cc];
__device__ float g_q[(size_t)Mm*Cc];
__device__ float g_k[(size_t)Mm*Cc];
__device__ float g_v[(size_t)Mm*Cc];
__device__ float g_att[(size_t)Mm*Cc];
__device__ float g_ffh[(size_t)Mm*FFd];
__device__ float g_wei[(size_t)Bb*Hh*Tt*Tt];   // 268 MB attention scores
__device__ float g_rowloss[Mm];
// bf16 split buffers: activations (A operand) and transposed weights (B operand)
__device__ __nv_bfloat16 g_ahi[(size_t)Mm*FFd];
__device__ __nv_bfloat16 g_alo[(size_t)Mm*FFd];
__device__ __nv_bfloat16 g_whi[(size_t)Vv*Cc];
__device__ __nv_bfloat16 g_wlo[(size_t)Vv*Cc];

// ---------------- warp-level MMA helpers (portable PTX, no arch-a gating) ----------------
__device__ __forceinline__ uint32_t smem_u32(const void* p) {
    uint32_t a;
    asm("{ .reg .u64 t; cvta.to.shared.u64 t, %1; cvt.u32.u64 %0, t; }" : "=r"(a) : "l"(p));
    return a;
}
__device__ __forceinline__ void ldsm4(uint32_t* r, uint32_t a) {
    asm volatile("ldmatrix.sync.aligned.m8n8.x4.shared.b16 {%0,%1,%2,%3}, [%4];"
        : "=r"(r[0]), "=r"(r[1]), "=r"(r[2]), "=r"(r[3]) : "r"(a));
}
__device__ __forceinline__ void mma16816(float* c, const uint32_t* a, uint32_t b0, uint32_t b1) {
    asm volatile("mma.sync.aligned.m16n8k16.row.col.f32.bf16.bf16.f32 "
        "{%0,%1,%2,%3}, {%4,%5,%6,%7}, {%8,%9}, {%0,%1,%2,%3};"
        : "+f"(c[0]), "+f"(c[1]), "+f"(c[2]), "+f"(c[3])
        : "r"(a[0]), "r"(a[1]), "r"(a[2]), "r"(a[3]), "r"(b0), "r"(b1));
}

// ---------------- helpers ----------------
__device__ __forceinline__ float block_reduce(float v, float* buf, bool ismax) {
    int tid = threadIdx.x;            // blockDim.x == 256
    buf[tid] = v;
    __syncthreads();
    #pragma unroll
    for (int s = 128; s > 0; s >>= 1) {
        if (tid < s) buf[tid] = ismax ? fmaxf(buf[tid], buf[tid + s]) : (buf[tid] + buf[tid + s]);
        __syncthreads();
    }
    float r = buf[0];
    __syncthreads();
    return r;
}

// ---------------- embed ----------------
__global__ void embed_k(const int* __restrict__ idx, const float* __restrict__ tok,
                        const float* __restrict__ pos, float* __restrict__ x) {
    int i4 = blockIdx.x * blockDim.x + threadIdx.x;
    if (i4 >= Mm * Cc / 4) return;
    int c  = (i4 % (Cc / 4)) * 4;
    int bt = i4 / (Cc / 4);
    int t  = bt % Tt;
    int tk = idx[bt];
    float4 a = *(const float4*)&tok[(size_t)tk * Cc + c];
    float4 p = *(const float4*)&pos[(size_t)t * Cc + c];
    a.x += p.x; a.y += p.y; a.z += p.z; a.w += p.w;
    *(float4*)&x[(size_t)bt * Cc + c] = a;
}

// ---------------- layernorm ----------------
__global__ void layernorm_k(const float* __restrict__ x, const float* __restrict__ g,
                            const float* __restrict__ b, float* __restrict__ y) {
    __shared__ float buf[256];
    int tid = threadIdx.x;
    const float* xr = x + (size_t)blockIdx.x * Cc;
    float*       yr = y + (size_t)blockIdx.x * Cc;
    float4 v = ((const float4*)xr)[tid];
    float s  = v.x + v.y + v.z + v.w;
    float sq = v.x*v.x + v.y*v.y + v.z*v.z + v.w*v.w;
    s  = block_reduce(s,  buf, false);
    sq = block_reduce(sq, buf, false);
    float mean = s * (1.0f / Cc);
    float var  = sq * (1.0f / Cc) - mean * mean;
    float r    = rsqrtf(var + 1e-5f);
    float4 gg = ((const float4*)g)[tid];
    float4 bb = ((const float4*)b)[tid];
    v.x = (v.x - mean) * r * gg.x + bb.x;
    v.y = (v.y - mean) * r * gg.y + bb.y;
    v.z = (v.z - mean) * r * gg.z + bb.z;
    v.w = (v.w - mean) * r * gg.w + bb.w;
    ((float4*)yr)[tid] = v;
}

// ---------------- fp32 -> bf16 hi/lo (elementwise, A operand) ----------------
__global__ void conv_act_k(const float* __restrict__ x, __nv_bfloat16* __restrict__ hi,
                           __nv_bfloat16* __restrict__ lo, int n4) {
    int i = blockIdx.x * blockDim.x + threadIdx.x;
    if (i >= n4) return;
    float4 v = ((const float4*)x)[i];
    __nv_bfloat16 h0 = __float2bfloat16(v.x), h1 = __float2bfloat16(v.y);
    __nv_bfloat16 h2 = __float2bfloat16(v.z), h3 = __float2bfloat16(v.w);
    __nv_bfloat16 l0 = __float2bfloat16(v.x - __bfloat162float(h0));
    __nv_bfloat16 l1 = __float2bfloat16(v.y - __bfloat162float(h1));
    __nv_bfloat16 l2 = __float2bfloat16(v.z - __bfloat162float(h2));
    __nv_bfloat16 l3 = __float2bfloat16(v.w - __bfloat162float(h3));
    uint2 wh, wl;
    wh.x = (uint32_t)__bfloat16_as_ushort(h0) | ((uint32_t)__bfloat16_as_ushort(h1) << 16);
    wh.y = (uint32_t)__bfloat16_as_ushort(h2) | ((uint32_t)__bfloat16_as_ushort(h3) << 16);
    wl.x = (uint32_t)__bfloat16_as_ushort(l0) | ((uint32_t)__bfloat16_as_ushort(l1) << 16);
    wl.y = (uint32_t)__bfloat16_as_ushort(l2) | ((uint32_t)__bfloat16_as_ushort(l3) << 16);
    *(uint2*)&hi[(size_t)i * 4] = wh;
    *(uint2*)&lo[(size_t)i * 4] = wl;
}

// ---------------- W [K,N] fp32 -> transposed [N,K] bf16 hi/lo (B operand) ----------------
__global__ void conv_wT_k(const float* __restrict__ W, int K, int N,
                          __nv_bfloat16* __restrict__ hi, __nv_bfloat16* __restrict__ lo) {
    __shared__ float t[32][33];
    int n0 = blockIdx.x * 32, k0 = blockIdx.y * 32;
    int tx = threadIdx.x & 31, ty = threadIdx.x >> 5;   // 256 threads: 32 x 8
    #pragma unroll
    for (int i = 0; i < 32; i += 8)
        t[ty + i][tx] = W[(size_t)(k0 + ty + i) * N + n0 + tx];
    __syncthreads();
    #pragma unroll
    for (int i = 0; i < 32; i += 8) {
        int n = ty + i;
        float x = t[tx][n];                          // W[k0+tx][n0+n]
        __nv_bfloat16 h = __float2bfloat16(x);
        __nv_bfloat16 l = __float2bfloat16(x - __bfloat162float(h));
        hi[(size_t)(n0 + n) * K + k0 + tx] = h;
        lo[(size_t)(n0 + n) * K + k0 + tx] = l;
    }
}

// ---------------- bf16x3 tensor-core GEMM: C[M,N] = op(A@B^T + bias + res) ----------------
// A: [M,K] bf16 hi/lo (K-contig). B: [N,K] bf16 hi/lo (K-contig, pre-transposed weights).
// CTA tile 128x128, BK=32, 256 threads (8 warps: 2 along M x 4 along N, warp tile 64x32).
// Smem rows padded to 40 halves (80B) -> conflict-free ldmatrix. Double buffered.
#define BKh      32
#define ROWH     40                    // padded halves per row
#define ARR_B    (128 * ROWH * 2)      // 10240 bytes per array
#define STAGE_B  (4 * ARR_B)           // Ah, Al, Bh, Bl
#define GEMM_SMEM (2 * STAGE_B)        // 81920

template<bool BIAS, bool RES, bool RELU>
__global__ void __launch_bounds__(256) gemm_tc(
    int K,
    const __nv_bfloat16* __restrict__ Ahi, const __nv_bfloat16* __restrict__ Alo,
    const __nv_bfloat16* __restrict__ Bhi, const __nv_bfloat16* __restrict__ Blo,
    const float* __restrict__ bias, const float* __restrict__ res, int ldr,
    float* __restrict__ C, int ldc)
{
    extern __shared__ __align__(16) char smem[];
    const uint32_t sbase = smem_u32(smem);
    const int tid  = threadIdx.x;
    const int lane = tid & 31;
    const int warp = tid >> 5;
    const int wm = warp & 1;           // 2 warps along M
    const int wn = warp >> 1;          // 4 warps along N
    const int m0 = wm * 64, n0 = wn * 32;
    const int rowBase = blockIdx.y * 128;
    const int colBase = blockIdx.x * 128;

    float acc[4][4][4];
    #pragma unroll
    for (int i = 0; i < 4; ++i)
        #pragma unroll
        for (int j = 0; j < 4; ++j)
            #pragma unroll
            for (int q = 0; q < 4; ++q) acc[i][j][q] = 0.f;

    const int NC = K / BKh;

    // per-thread global load pattern: p in 0..7, arr = p>>1 (Ah,Al,Bh,Bl),
    // row = ((p&1)<<6) + (tid>>2), c8 = (tid&3)<<3
    const int lrow = tid >> 2;
    const int lc8  = (tid & 3) << 3;

    uint4 v[8];
    {   // prefetch chunk 0
        #pragma unroll
        for (int p = 0; p < 8; ++p) {
            int arr = p >> 1;
            int row = ((p & 1) << 6) + lrow;
            const __nv_bfloat16* src = (arr == 0) ? Ahi : (arr == 1) ? Alo
                                      : (arr == 2) ? Bhi : Blo;
            int rb = (arr < 2) ? rowBase : colBase;
            v[p] = *(const uint4*)(src + (size_t)(rb + row) * K + lc8);
        }
        #pragma unroll
        for (int p = 0; p < 8; ++p) {
            int arr = p >> 1;
            int row = ((p & 1) << 6) + lrow;
            *(uint4*)(smem + arr * ARR_B + (row * ROWH + lc8) * 2) = v[p];
        }
    }
    __syncthreads();

    // ldmatrix lane addressing (halves): (row16 + (lane&15))*ROWH + ks*16 + (lane>>4)*8
    const int lr16 = lane & 15;
    const int lk8  = (lane >> 4) << 3;

    for (int c = 0; c < NC; ++c) {
        const uint32_t st = sbase + (uint32_t)(c & 1) * STAGE_B;

        if (c + 1 < NC) {
            int k0 = (c + 1) * BKh;
            #pragma unroll
            for (int p = 0; p < 8; ++p) {
                int arr = p >> 1;
                int row = ((p & 1) << 6) + lrow;
                const __nv_bfloat16* src = (arr == 0) ? Ahi : (arr == 1) ? Alo
                                          : (arr == 2) ? Bhi : Blo;
                int rb = (arr < 2) ? rowBase : colBase;
                v[p] = *(const uint4*)(src + (size_t)(rb + row) * K + k0 + lc8);
            }
        }

        #pragma unroll
        for (int ks = 0; ks < 2; ++ks) {
            // B fragments: two ldmatrix.x4 per precision (n0..n15, n16..n31)
            uint32_t bh[2][4], bl[2][4];
            #pragma unroll
            for (int np = 0; np < 2; ++np) {
                uint32_t off = ((n0 + np * 16 + lr16) * ROWH + ks * 16 + lk8) * 2;
                ldsm4(bh[np], st + 2 * ARR_B + off);
                ldsm4(bl[np], st + 3 * ARR_B + off);
            }
            #pragma unroll
            for (int mf = 0; mf < 4; ++mf) {
                uint32_t ah[4], al[4];
                uint32_t off = ((m0 + mf * 16 + lr16) * ROWH + ks * 16 + lk8) * 2;
                ldsm4(ah, st + off);
                ldsm4(al, st + ARR_B + off);
                #pragma unroll
                for (int nf = 0; nf < 4; ++nf) {
                    int np = nf >> 1, sub = nf & 1;
                    uint32_t b0h = bh[np][sub],     b1h = bh[np][sub + 2];
                    uint32_t b0l = bl[np][sub],     b1l = bl[np][sub + 2];
                    mma16816(acc[mf][nf], ah, b0h, b1h);
                    mma16816(acc[mf][nf], ah, b0l, b1l);
                    mma16816(acc[mf][nf], al, b0h, b1h);
                }
            }
        }

        if (c + 1 < NC) {
            char* stn = smem + ((c + 1) & 1) * STAGE_B;
            #pragma unroll
            for (int p = 0; p < 8; ++p) {
                int arr = p >> 1;
                int row = ((p & 1) << 6) + lrow;
                *(uint4*)(stn + arr * ARR_B + (row * ROWH + lc8) * 2) = v[p];
            }
            __syncthreads();
        }
    }

    // Epilogue: registers -> global. c0,c1 at (r, col), c2,c3 at (r+8, col).
    const int erow = lane >> 2;
    const int ecol = (lane & 3) << 1;
    #pragma unroll
    for (int mf = 0; mf < 4; ++mf) {
        #pragma unroll
        for (int nf = 0; nf < 4; ++nf) {
            int row = rowBase + m0 + mf * 16 + erow;
            int col = colBase + n0 + nf * 8 + ecol;
            #pragma unroll
            for (int half = 0; half < 2; ++half) {
                int r = row + half * 8;
                float2 o;
                o.x = acc[mf][nf][half * 2 + 0];
                o.y = acc[mf][nf][half * 2 + 1];
                if (BIAS) {
                    float2 bv = *(const float2*)&bias[col];
                    o.x += bv.x; o.y += bv.y;
                }
                if (RES) {
                    float2 rv = *(const float2*)&res[(size_t)r * ldr + col];
                    o.x += rv.x; o.y += rv.y;
                }
                if (RELU) { o.x = fmaxf(o.x, 0.f); o.y = fmaxf(o.y, 0.f); }
                *(float2*)&C[(size_t)r * ldc + col] = o;
            }
        }
    }
}

// ---------------- attention scores: S = scale * Q K^T, causal mask ----------------
__global__ void __launch_bounds__(256) attn_scores_k(
    const float* __restrict__ q, const float* __restrict__ k, float* __restrict__ wei)
{
    int bh   = blockIdx.z;
    int b    = bh / Hh, h = bh % Hh;
    int row0 = blockIdx.y * 64, col0 = blockIdx.x * 64;
    float* W = wei + (size_t)bh * Tt * Tt;
    int tid = threadIdx.x;

    if (col0 > row0 + 63) {
        #pragma unroll
        for (int p = 0; p < 4; ++p) {
            int idx = tid + 256 * p;
            int r = idx >> 4, c4 = (idx & 15) * 4;
            float4 ninf = make_float4(-INFINITY, -INFINITY, -INFINITY, -INFINITY);
            *(float4*)&W[(size_t)(row0 + r) * Tt + col0 + c4] = ninf;
        }
        return;
    }

    __shared__ float Qs[64][64];
    __shared__ float KsT[64][64];
    const float* Qb = q + (size_t)b * Tt * Cc + h * HSs;
    const float* Kb = k + (size_t)b * Tt * Cc + h * HSs;

    #pragma unroll
    for (int p = 0; p < 4; ++p) {
        int idx = tid + 256 * p;
        int r = idx >> 4, c4 = (idx & 15) * 4;
        float4 vq = *(const float4*)&Qb[(size_t)(row0 + r) * Cc + c4];
        *(float4*)&Qs[r][c4] = vq;
        float4 vk = *(const float4*)&Kb[(size_t)(col0 + r) * Cc + c4];
        KsT[c4 + 0][r] = vk.x; KsT[c4 + 1][r] = vk.y;
        KsT[c4 + 2][r] = vk.z; KsT[c4 + 3][r] = vk.w;
    }
    __syncthreads();

    int tx = tid & 15, ty = tid >> 4;
    float acc[4][4] = {};
    #pragma unroll 8
    for (int d = 0; d < 64; ++d) {
        float a[4];
        #pragma unroll
        for (int i = 0; i < 4; ++i) a[i] = Qs[ty * 4 + i][d];
        float4 bv = *(const float4*)&KsT[d][tx * 4];
        #pragma unroll
        for (int i = 0; i < 4; ++i) {
            acc[i][0] += a[i] * bv.x; acc[i][1] += a[i] * bv.y;
            acc[i][2] += a[i] * bv.z; acc[i][3] += a[i] * bv.w;
        }
    }

    const float scale = 0.125f;
    #pragma unroll
    for (int i = 0; i < 4; ++i) {
        int r = row0 + ty * 4 + i;
        int c = col0 + tx * 4;
        float4 o;
        o.x = (c + 0 <= r) ? acc[i][0] * scale : -INFINITY;
        o.y = (c + 1 <= r) ? acc[i][1] * scale : -INFINITY;
        o.z = (c + 2 <= r) ? acc[i][2] * scale : -INFINITY;
        o.w = (c + 3 <= r) ? acc[i][3] * scale : -INFINITY;
        *(float4*)&W[(size_t)r * Tt + c] = o;
    }
}

// ---------------- row softmax (in place) ----------------
__global__ void softmax_rows_k(float* __restrict__ wei) {
    __shared__ float buf[256];
    float* W = wei + (size_t)blockIdx.x * Tt;
    int tid = threadIdx.x;
    float4 v = ((const float4*)W)[tid];
    float m = fmaxf(fmaxf(v.x, v.y), fmaxf(v.z, v.w));
    m = block_reduce(m, buf, true);
    float4 e;
    e.x = expf(v.x - m); e.y = expf(v.y - m);
    e.z = expf(v.z - m); e.w = expf(v.w - m);
    float s = e.x + e.y + e.z + e.w;
    s = block_reduce(s, buf, false);
    float inv = 1.0f / s;
    e.x *= inv; e.y *= inv; e.z *= inv; e.w *= inv;
    ((float4*)W)[tid] = e;
}

// ---------------- AV: out = softmax(S) @ V ----------------
__global__ void __launch_bounds__(256) attn_av_k(
    const float* __restrict__ wei, const float* __restrict__ v, float* __restrict__ out)
{
    int bh = blockIdx.y;
    int b  = bh / Hh, h = bh % Hh;
    int row0 = blockIdx.x * 64;
    const float* Wb = wei + (size_t)bh * Tt * Tt;
    const float* Vb = v   + (size_t)b * Tt * Cc + h * HSs;
    float*       Ob = out + (size_t)b * Tt * Cc + h * HSs;

    __shared__ float Ws[64][36];
    __shared__ float Vs[32][64];
    int tid = threadIdx.x;
    int tx = tid & 15, ty = tid >> 4;
    float acc[4][4] = {};

    int kmax = row0 + 64;
    for (int k0 = 0; k0 < kmax; k0 += 32) {
        #pragma unroll
        for (int p = 0; p < 2; ++p) {
            int idx = tid + 256 * p;
            int r  = idx >> 3;
            int c4 = (idx & 7) * 4;
            float4 vw = *(const float4*)&Wb[(size_t)(row0 + r) * Tt + k0 + c4];
            *(float4*)&Ws[r][c4] = vw;
            int rv  = idx >> 4;
            int cv4 = (idx & 15) * 4;
            float4 vv = *(const float4*)&Vb[(size_t)(k0 + rv) * Cc + cv4];
            *(float4*)&Vs[rv][cv4] = vv;
        }
        __syncthreads();
        #pragma unroll 8
        for (int k = 0; k < 32; ++k) {
            float a[4];
            #pragma unroll
            for (int i = 0; i < 4; ++i) a[i] = Ws[ty * 4 + i][k];
            float4 bv = *(const float4*)&Vs[k][tx * 4];
            #pragma unroll
            for (int i = 0; i < 4; ++i) {
                acc[i][0] += a[i] * bv.x; acc[i][1] += a[i] * bv.y;
                acc[i][2] += a[i] * bv.z; acc[i][3] += a[i] * bv.w;
            }
        }
        __syncthreads();
    }

    #pragma unroll
    for (int i = 0; i < 4; ++i) {
        float4 o; o.x = acc[i][0]; o.y = acc[i][1]; o.z = acc[i][2]; o.w = acc[i][3];
        *(float4*)&Ob[(size_t)(row0 + ty * 4 + i) * Cc + tx * 4] = o;
    }
}

// ---------------- loss ----------------
__global__ void loss_rows_k(const float* __restrict__ logits, const int* __restrict__ targets,
                            float* __restrict__ rowloss) {
    __shared__ float buf[256];
    const float* L = logits + (size_t)blockIdx.x * Vv;
    int tid = threadIdx.x;
    const int V4 = Vv / 4;
    float m = -INFINITY;
    for (int j = tid; j < V4; j += 256) {
        float4 v = ((const float4*)L)[j];
        m = fmaxf(m, fmaxf(fmaxf(v.x, v.y), fmaxf(v.z, v.w)));
    }
    m = block_reduce(m, buf, true);
    float s = 0.f;
    for (int j = tid; j < V4; j += 256) {
        float4 v = ((const float4*)L)[j];
        s += expf(v.x - m) + expf(v.y - m) + expf(v.z - m) + expf(v.w - m);
    }
    s = block_reduce(s, buf, false);
    if (tid == 0) rowloss[blockIdx.x] = logf(s) + m - L[targets[blockIdx.x]];
}

__global__ void loss_reduce_k(const float* __restrict__ rowloss, float* __restrict__ out) {
    __shared__ float buf[256];
    int tid = threadIdx.x;
    float s = 0.f;
    for (int j = tid; j < Mm; j += 256) s += rowloss[j];
    s = block_reduce(s, buf, false);
    if (tid == 0) out[0] = s / (float)Mm;
}

// ---------------- launch ----------------
extern "C" void kernel_launch(void* const* d_in, const int* in_sizes, int n_in,
                              void* d_out, int out_size)
{
    const int*   idx     = (const int*)d_in[0];
    const int*   targets = (const int*)d_in[1];
    const float* tok_emb = (const float*)d_in[2];
    const float* pos_emb = (const float*)d_in[3];
    const float* ln1_g   = (const float*)d_in[4];
    const float* ln1_b   = (const float*)d_in[5];
    const float* Wq      = (const float*)d_in[6];
    const float* Wk      = (const float*)d_in[7];
    const float* Wv      = (const float*)d_in[8];
    const float* Wo      = (const float*)d_in[9];
    const float* bo      = (const float*)d_in[10];
    const float* ln2_g   = (const float*)d_in[11];
    const float* ln2_b   = (const float*)d_in[12];
    const float* W1      = (const float*)d_in[13];
    const float* b1      = (const float*)d_in[14];
    const float* W2      = (const float*)d_in[15];
    const float* b2      = (const float*)d_in[16];
    const float* lnf_g   = (const float*)d_in[17];
    const float* lnf_b   = (const float*)d_in[18];
    const float* Wlm     = (const float*)d_in[19];
    const float* blm     = (const float*)d_in[20];
    float* out = (float*)d_out;

    float *px, *ph, *pq, *pk, *pv, *patt, *pffh, *pwei, *prl;
    __nv_bfloat16 *pahi, *palo, *pwhi, *pwlo;
    cudaGetSymbolAddress((void**)&px,   g_x);
    cudaGetSymbolAddress((void**)&ph,   g_h);
    cudaGetSymbolAddress((void**)&pq,   g_q);
    cudaGetSymbolAddress((void**)&pk,   g_k);
    cudaGetSymbolAddress((void**)&pv,   g_v);
    cudaGetSymbolAddress((void**)&patt, g_att);
    cudaGetSymbolAddress((void**)&pffh, g_ffh);
    cudaGetSymbolAddress((void**)&pwei, g_wei);
    cudaGetSymbolAddress((void**)&prl,  g_rowloss);
    cudaGetSymbolAddress((void**)&pahi, g_ahi);
    cudaGetSymbolAddress((void**)&palo, g_alo);
    cudaGetSymbolAddress((void**)&pwhi, g_whi);
    cudaGetSymbolAddress((void**)&pwlo, g_wlo);

    cudaFuncSetAttribute(gemm_tc<false,false,false>, cudaFuncAttributeMaxDynamicSharedMemorySize, GEMM_SMEM);
    cudaFuncSetAttribute(gemm_tc<true,true,false>,   cudaFuncAttributeMaxDynamicSharedMemorySize, GEMM_SMEM);
    cudaFuncSetAttribute(gemm_tc<true,false,true>,   cudaFuncAttributeMaxDynamicSharedMemorySize, GEMM_SMEM);
    cudaFuncSetAttribute(gemm_tc<true,false,false>,  cudaFuncAttributeMaxDynamicSharedMemorySize, GEMM_SMEM);

    embed_k<<<(Mm * Cc / 4 + 255) / 256, 256>>>(idx, tok_emb, pos_emb, px);

    dim3 gC(Cc / 128, Mm / 128);       // 8 x 32
    dim3 gF(FFd / 128, Mm / 128);      // 32 x 32
    dim3 gV(Vv / 128, Mm / 128);       // 393 x 32
    dim3 gS(Tt / 64, Tt / 64, Bb * Hh);
    dim3 gA(Tt / 64, Bb * Hh);
    const int n4C = Mm * Cc / 4, n4F = Mm * FFd / 4;

    for (int l = 0; l < Ll; ++l) {
        const size_t oCC = (size_t)l * Cc * Cc;
        const size_t oC  = (size_t)l * Cc;
        const size_t oCF = (size_t)l * Cc * FFd;
        const size_t oF  = (size_t)l * FFd;

        layernorm_k<<<Mm, 256>>>(px, ln1_g + oC, ln1_b + oC, ph);
        conv_act_k<<<(n4C + 255) / 256, 256>>>(ph, pahi, palo, n4C);

        conv_wT_k<<<dim3(Cc / 32, Cc / 32), 256>>>(Wq + oCC, Cc, Cc, pwhi, pwlo);
        gemm_tc<false,false,false><<<gC, 256, GEMM_SMEM>>>(Cc, pahi, palo, pwhi, pwlo,
                                                           nullptr, nullptr, 0, pq, Cc);
        conv_wT_k<<<dim3(Cc / 32, Cc / 32), 256>>>(Wk + oCC, Cc, Cc, pwhi, pwlo);
        gemm_tc<false,false,false><<<gC, 256, GEMM_SMEM>>>(Cc, pahi, palo, pwhi, pwlo,
                                                           nullptr, nullptr, 0, pk, Cc);
        conv_wT_k<<<dim3(Cc / 32, Cc / 32), 256>>>(Wv + oCC, Cc, Cc, pwhi, pwlo);
        gemm_tc<false,false,false><<<gC, 256, GEMM_SMEM>>>(Cc, pahi, palo, pwhi, pwlo,
                                                           nullptr, nullptr, 0, pv, Cc);

        attn_scores_k<<<gS, 256>>>(pq, pk, pwei);
        softmax_rows_k<<<Bb * Hh * Tt, 256>>>(pwei);
        attn_av_k<<<gA, 256>>>(pwei, pv, patt);

        conv_act_k<<<(n4C + 255) / 256, 256>>>(patt, pahi, palo, n4C);
        conv_wT_k<<<dim3(Cc / 32, Cc / 32), 256>>>(Wo + oCC, Cc, Cc, pwhi, pwlo);
        gemm_tc<true,true,false><<<gC, 256, GEMM_SMEM>>>(Cc, pahi, palo, pwhi, pwlo,
                                                         bo + oC, px, Cc, px, Cc);

        layernorm_k<<<Mm, 256>>>(px, ln2_g + oC, ln2_b + oC, ph);
        conv_act_k<<<(n4C + 255) / 256, 256>>>(ph, pahi, palo, n4C);
        conv_wT_k<<<dim3(FFd / 32, Cc / 32), 256>>>(W1 + oCF, Cc, FFd, pwhi, pwlo);
        gemm_tc<true,false,true><<<gF, 256, GEMM_SMEM>>>(Cc, pahi, palo, pwhi, pwlo,
                                                         b1 + oF, nullptr, 0, pffh, FFd);

        conv_act_k<<<(n4F + 255) / 256, 256>>>(pffh, pahi, palo, n4F);
        conv_wT_k<<<dim3(Cc / 32, FFd / 32), 256>>>(W2 + oCF, FFd, Cc, pwhi, pwlo);
        gemm_tc<true,true,false><<<gC, 256, GEMM_SMEM>>>(FFd, pahi, palo, pwhi, pwlo,
                                                         b2 + oC, px, Cc, px, Cc);
    }

    // final LN + LM head -> logits into d_out
    layernorm_k<<<Mm, 256>>>(px, lnf_g, lnf_b, ph);
    conv_act_k<<<(n4C + 255) / 256, 256>>>(ph, pahi, palo, n4C);
    conv_wT_k<<<dim3(Vv / 32, Cc / 32), 256>>>(Wlm, Cc, Vv, pwhi, pwlo);
    gemm_tc<true,false,false><<<gV, 256, GEMM_SMEM>>>(Cc, pahi, palo, pwhi, pwlo,
                                                      blm, nullptr, 0, out, Vv);

    long long logitsN = (long long)Mm * Vv;
    if ((long long)out_size > logitsN) {
        loss_rows_k<<<Mm, 256>>>(out, targets, prl);
        loss_reduce_k<<<1, 256>>>(prl, out + logitsN);
    }
}

// round 7
// speedup vs baseline: 2.0610x; 1.0516x over previous
#include <cuda_runtime.h>
#include <cuda_bf16.h>
#include <math.h>
#include <stdint.h>

// Problem constants
#define Bb 4
#define Tt 1024
#define Cc 1024
#define Hh 16
#define HSs 64
#define Ll 12
#define Vv 50304
#define Mm (Bb*Tt)      // 4096
#define FFd (4*Cc)      // 4096

typedef __nv_bfloat16 bf16;

// ---------------- scratch (static device memory; no allocations) ----------------
__device__ float g_x[(size_t)Mm*Cc];
__device__ float g_wei[(size_t)Bb*Hh*Tt*Tt];     // fp32 attention scores (268MB)
__device__ float g_rowloss[Mm];
__device__ bf16 g_hhi[(size_t)Mm*Cc];
__device__ bf16 g_hlo[(size_t)Mm*Cc];
__device__ bf16 g_qkvhi[(size_t)Mm*3072];
__device__ bf16 g_qkvlo[(size_t)Mm*3072];
__device__ bf16 g_phi[(size_t)Bb*Hh*Tt*Tt];      // softmax probs hi (134MB)
__device__ bf16 g_plo[(size_t)Bb*Hh*Tt*Tt];
__device__ bf16 g_atthi[(size_t)Mm*Cc];
__device__ bf16 g_attlo[(size_t)Mm*Cc];
__device__ bf16 g_ffhhi[(size_t)Mm*FFd];
__device__ bf16 g_ffhlo[(size_t)Mm*FFd];
__device__ bf16 g_whi[(size_t)Vv*Cc];
__device__ bf16 g_wlo[(size_t)Vv*Cc];

// ---------------- PTX helpers (portable, no arch-a gating) ----------------
__device__ __forceinline__ uint32_t smem_u32(const void* p) {
    uint32_t a;
    asm("{ .reg .u64 t; cvta.to.shared.u64 t, %1; cvt.u32.u64 %0, t; }" : "=r"(a) : "l"(p));
    return a;
}
__device__ __forceinline__ void ldsm4(uint32_t* r, uint32_t a) {
    asm volatile("ldmatrix.sync.aligned.m8n8.x4.shared.b16 {%0,%1,%2,%3}, [%4];"
        : "=r"(r[0]), "=r"(r[1]), "=r"(r[2]), "=r"(r[3]) : "r"(a));
}
__device__ __forceinline__ void ldsm4t(uint32_t* r, uint32_t a) {
    asm volatile("ldmatrix.sync.aligned.m8n8.x4.trans.shared.b16 {%0,%1,%2,%3}, [%4];"
        : "=r"(r[0]), "=r"(r[1]), "=r"(r[2]), "=r"(r[3]) : "r"(a));
}
__device__ __forceinline__ void mma16816(float* c, const uint32_t* a, uint32_t b0, uint32_t b1) {
    asm volatile("mma.sync.aligned.m16n8k16.row.col.f32.bf16.bf16.f32 "
        "{%0,%1,%2,%3}, {%4,%5,%6,%7}, {%8,%9}, {%0,%1,%2,%3};"
        : "+f"(c[0]), "+f"(c[1]), "+f"(c[2]), "+f"(c[3])
        : "r"(a[0]), "r"(a[1]), "r"(a[2]), "r"(a[3]), "r"(b0), "r"(b1));
}
__device__ __forceinline__ void cpa16(uint32_t saddr, const void* g) {
    asm volatile("cp.async.cg.shared.global [%0], [%1], 16;" :: "r"(saddr), "l"(g));
}
#define CPCOMMIT() asm volatile("cp.async.commit_group;" ::: "memory")
#define CPWAIT1()  asm volatile("cp.async.wait_group 1;" ::: "memory")
#define CPWAIT0()  asm volatile("cp.async.wait_group 0;" ::: "memory")

__device__ __forceinline__ void split2(float x, bf16& h, bf16& l) {
    h = __float2bfloat16(x);
    l = __float2bfloat16(x - __bfloat162float(h));
}
__device__ __forceinline__ uint32_t packbf(bf16 a, bf16 b) {
    return (uint32_t)__bfloat16_as_ushort(a) | ((uint32_t)__bfloat16_as_ushort(b) << 16);
}

// ---------------- helpers ----------------
__device__ __forceinline__ float block_reduce(float v, float* buf, bool ismax) {
    int tid = threadIdx.x;            // blockDim.x == 256
    buf[tid] = v;
    __syncthreads();
    #pragma unroll
    for (int s = 128; s > 0; s >>= 1) {
        if (tid < s) buf[tid] = ismax ? fmaxf(buf[tid], buf[tid + s]) : (buf[tid] + buf[tid + s]);
        __syncthreads();
    }
    float r = buf[0];
    __syncthreads();
    return r;
}

// ---------------- embed ----------------
__global__ void embed_k(const int* __restrict__ idx, const float* __restrict__ tok,
                        const float* __restrict__ pos, float* __restrict__ x) {
    int i4 = blockIdx.x * blockDim.x + threadIdx.x;
    if (i4 >= Mm * Cc / 4) return;
    int c  = (i4 % (Cc / 4)) * 4;
    int bt = i4 / (Cc / 4);
    int t  = bt % Tt;
    int tk = idx[bt];
    float4 a = *(const float4*)&tok[(size_t)tk * Cc + c];
    float4 p = *(const float4*)&pos[(size_t)t * Cc + c];
    a.x += p.x; a.y += p.y; a.z += p.z; a.w += p.w;
    *(float4*)&x[(size_t)bt * Cc + c] = a;
}

// ---------------- layernorm: fp32 in, bf16 hi/lo out ----------------
__global__ void layernorm_split_k(const float* __restrict__ x, const float* __restrict__ g,
                                  const float* __restrict__ b,
                                  bf16* __restrict__ yhi, bf16* __restrict__ ylo) {
    __shared__ float buf[256];
    int tid = threadIdx.x;
    const float* xr = x + (size_t)blockIdx.x * Cc;
    float4 v = ((const float4*)xr)[tid];
    float s  = v.x + v.y + v.z + v.w;
    float sq = v.x*v.x + v.y*v.y + v.z*v.z + v.w*v.w;
    s  = block_reduce(s,  buf, false);
    sq = block_reduce(sq, buf, false);
    float mean = s * (1.0f / Cc);
    float var  = sq * (1.0f / Cc) - mean * mean;
    float r    = rsqrtf(var + 1e-5f);
    float4 gg = ((const float4*)g)[tid];
    float4 bb = ((const float4*)b)[tid];
    float o0 = (v.x - mean) * r * gg.x + bb.x;
    float o1 = (v.y - mean) * r * gg.y + bb.y;
    float o2 = (v.z - mean) * r * gg.z + bb.z;
    float o3 = (v.w - mean) * r * gg.w + bb.w;
    bf16 h0,l0,h1,l1,h2,l2,h3,l3;
    split2(o0,h0,l0); split2(o1,h1,l1); split2(o2,h2,l2); split2(o3,h3,l3);
    uint2 wh, wl;
    wh.x = packbf(h0,h1); wh.y = packbf(h2,h3);
    wl.x = packbf(l0,l1); wl.y = packbf(l2,l3);
    ((uint2*)(yhi + (size_t)blockIdx.x * Cc))[tid] = wh;
    ((uint2*)(ylo + (size_t)blockIdx.x * Cc))[tid] = wl;
}

// ---------------- W [K,N] fp32 -> transposed [N,K] bf16 hi/lo at row offset ----------------
__global__ void conv_wT_k(const float* __restrict__ W, int K, int N, int n_off,
                          bf16* __restrict__ hi, bf16* __restrict__ lo) {
    __shared__ float t[32][33];
    int n0 = blockIdx.x * 32, k0 = blockIdx.y * 32;
    int tx = threadIdx.x & 31, ty = threadIdx.x >> 5;   // 256 threads: 32 x 8
    #pragma unroll
    for (int i = 0; i < 32; i += 8)
        t[ty + i][tx] = W[(size_t)(k0 + ty + i) * N + n0 + tx];
    __syncthreads();
    #pragma unroll
    for (int i = 0; i < 32; i += 8) {
        int n = ty + i;
        float x = t[tx][n];                          // W[k0+tx][n0+n]
        bf16 h, l;
        split2(x, h, l);
        hi[(size_t)(n_off + n0 + n) * K + k0 + tx] = h;
        lo[(size_t)(n_off + n0 + n) * K + k0 + tx] = l;
    }
}

// ---------------- bf16x3 tensor-core GEMM, cp.async 3-stage pipeline ----------------
// A: [M,K] bf16 hi/lo (K-contig, lda==K). B: [N,K] bf16 hi/lo (pre-transposed).
// CTA tile 128x128, BK=32, 256 threads (8 warps, warp tile 64x32).
#define BKh      32
#define ROWH     40
#define ARR_B    (128 * ROWH * 2)      // 10240 B
#define STAGE_B  (4 * ARR_B)           // 40960 B
#define GEMM_SMEM (3 * STAGE_B)        // 122880 B

__device__ __forceinline__ void issue_stage(
    uint32_t sbase, int buf, int tid, int rowBase, int colBase, int K, int k0,
    const bf16* __restrict__ Ahi, const bf16* __restrict__ Alo,
    const bf16* __restrict__ Bhi, const bf16* __restrict__ Blo)
{
    const int lrow = tid >> 2;
    const int lc8  = (tid & 3) << 3;
    uint32_t sb = sbase + (uint32_t)buf * STAGE_B;
    #pragma unroll
    for (int p = 0; p < 8; ++p) {
        int arr = p >> 1;
        int row = ((p & 1) << 6) + lrow;
        const bf16* src = (arr == 0) ? Ahi : (arr == 1) ? Alo : (arr == 2) ? Bhi : Blo;
        int rb = (arr < 2) ? rowBase : colBase;
        cpa16(sb + arr * ARR_B + (row * ROWH + lc8) * 2,
              src + (size_t)(rb + row) * K + k0 + lc8);
    }
}

template<bool SPLIT, bool BIAS, bool RES, bool RELU>
__global__ void __launch_bounds__(256) gemm_tc(
    int K,
    const bf16* __restrict__ Ahi, const bf16* __restrict__ Alo,
    const bf16* __restrict__ Bhi, const bf16* __restrict__ Blo,
    const float* __restrict__ bias, const float* __restrict__ res, int ldr,
    float* __restrict__ C, bf16* __restrict__ Chi, bf16* __restrict__ Clo, int ldc)
{
    extern __shared__ __align__(16) char smem[];
    const uint32_t sbase = smem_u32(smem);
    const int tid  = threadIdx.x;
    const int lane = tid & 31;
    const int warp = tid >> 5;
    const int m0 = (warp & 1) * 64, n0 = (warp >> 1) * 32;
    const int rowBase = blockIdx.y * 128;
    const int colBase = blockIdx.x * 128;

    float acc[4][4][4];
    #pragma unroll
    for (int i = 0; i < 4; ++i)
        #pragma unroll
        for (int j = 0; j < 4; ++j)
            #pragma unroll
            for (int q = 0; q < 4; ++q) acc[i][j][q] = 0.f;

    const int NC = K / BKh;

    issue_stage(sbase, 0, tid, rowBase, colBase, K, 0, Ahi, Alo, Bhi, Blo);
    CPCOMMIT();
    issue_stage(sbase, 1, tid, rowBase, colBase, K, BKh, Ahi, Alo, Bhi, Blo);
    CPCOMMIT();

    const int lr16 = lane & 15;
    const int lk8  = (lane >> 4) << 3;
    int buf = 0, nbuf = 2;

    for (int c = 0; c < NC; ++c) {
        if (c + 1 < NC) { CPWAIT1(); } else { CPWAIT0(); }
        __syncthreads();
        if (c + 2 < NC) {
            issue_stage(sbase, nbuf, tid, rowBase, colBase, K, (c + 2) * BKh, Ahi, Alo, Bhi, Blo);
            CPCOMMIT();
            nbuf = (nbuf + 1 == 3) ? 0 : nbuf + 1;
        }
        const uint32_t st = sbase + (uint32_t)buf * STAGE_B;
        buf = (buf + 1 == 3) ? 0 : buf + 1;

        #pragma unroll
        for (int ks = 0; ks < 2; ++ks) {
            uint32_t bh[2][4], bl[2][4];
            #pragma unroll
            for (int np = 0; np < 2; ++np) {
                uint32_t off = ((n0 + np * 16 + lr16) * ROWH + ks * 16 + lk8) * 2;
                ldsm4(bh[np], st + 2 * ARR_B + off);
                ldsm4(bl[np], st + 3 * ARR_B + off);
            }
            #pragma unroll
            for (int mf = 0; mf < 4; ++mf) {
                uint32_t ah[4], al[4];
                uint32_t off = ((m0 + mf * 16 + lr16) * ROWH + ks * 16 + lk8) * 2;
                ldsm4(ah, st + off);
                ldsm4(al, st + ARR_B + off);
                #pragma unroll
                for (int nf = 0; nf < 4; ++nf) {
                    int np = nf >> 1, sub = nf & 1;
                    mma16816(acc[mf][nf], ah, bh[np][sub], bh[np][sub + 2]);
                    mma16816(acc[mf][nf], ah, bl[np][sub], bl[np][sub + 2]);
                    mma16816(acc[mf][nf], al, bh[np][sub], bh[np][sub + 2]);
                }
            }
        }
        __syncthreads();
    }

    const int erow = lane >> 2;
    const int ecol = (lane & 3) << 1;
    #pragma unroll
    for (int mf = 0; mf < 4; ++mf) {
        #pragma unroll
        for (int nf = 0; nf < 4; ++nf) {
            int row = rowBase + m0 + mf * 16 + erow;
            int col = colBase + n0 + nf * 8 + ecol;
            #pragma unroll
            for (int half = 0; half < 2; ++half) {
                int r = row + half * 8;
                float ox = acc[mf][nf][half * 2 + 0];
                float oy = acc[mf][nf][half * 2 + 1];
                if (BIAS) {
                    float2 bv = *(const float2*)&bias[col];
                    ox += bv.x; oy += bv.y;
                }
                if (RES) {
                    float2 rv = *(const float2*)&res[(size_t)r * ldr + col];
                    ox += rv.x; oy += rv.y;
                }
                if (RELU) { ox = fmaxf(ox, 0.f); oy = fmaxf(oy, 0.f); }
                if (SPLIT) {
                    bf16 h0,l0,h1,l1;
                    split2(ox,h0,l0); split2(oy,h1,l1);
                    *(uint32_t*)&Chi[(size_t)r * ldc + col] = packbf(h0,h1);
                    *(uint32_t*)&Clo[(size_t)r * ldc + col] = packbf(l0,l1);
                } else {
                    float2 o; o.x = ox; o.y = oy;
                    *(float2*)&C[(size_t)r * ldc + col] = o;
                }
            }
        }
    }
}

// ---------------- attention scores (bf16x3 MMA): S = 0.125 * Q K^T, causal ----------------
// block 128 thr (4 warps), tile 64x64, K=HS=64. Only causal tiles computed.
#define SROWH 72
__global__ void __launch_bounds__(128) attn_scores_mma(
    const bf16* __restrict__ qkvhi, const bf16* __restrict__ qkvlo,
    float* __restrict__ wei)
{
    int row0 = blockIdx.y * 64, col0 = blockIdx.x * 64;
    if (col0 > row0) return;
    int bh = blockIdx.z;
    int b = bh >> 4, h = bh & 15;
    __shared__ bf16 sm[4][64][SROWH];   // Qh Ql Kh Kl
    int tid = threadIdx.x, lane = tid & 31, warp = tid >> 5;
    const size_t qbase = (size_t)b * Tt * 3072 + h * 64;
    const size_t kbase = qbase + 1024;

    #pragma unroll
    for (int p = 0; p < 4; ++p) {
        int idx = tid + p * 128;       // 0..511
        int r = idx >> 3, c8 = (idx & 7) * 8;
        *(uint4*)&sm[0][r][c8] = *(const uint4*)(qkvhi + qbase + (size_t)(row0 + r) * 3072 + c8);
        *(uint4*)&sm[1][r][c8] = *(const uint4*)(qkvlo + qbase + (size_t)(row0 + r) * 3072 + c8);
        *(uint4*)&sm[2][r][c8] = *(const uint4*)(qkvhi + kbase + (size_t)(col0 + r) * 3072 + c8);
        *(uint4*)&sm[3][r][c8] = *(const uint4*)(qkvlo + kbase + (size_t)(col0 + r) * 3072 + c8);
    }
    __syncthreads();

    const uint32_t sb = smem_u32(sm);
    const int m0 = warp * 16;
    const int lr16 = lane & 15, lk8 = (lane >> 4) << 3;
    float acc[8][4];
    #pragma unroll
    for (int i = 0; i < 8; ++i)
        #pragma unroll
        for (int q = 0; q < 4; ++q) acc[i][q] = 0.f;

    #pragma unroll
    for (int ks = 0; ks < 4; ++ks) {
        uint32_t ah[4], al[4];
        uint32_t aoff = ((m0 + lr16) * SROWH + ks * 16 + lk8) * 2;
        ldsm4(ah, sb + aoff);
        ldsm4(al, sb + 64 * SROWH * 2 + aoff);
        uint32_t kh[4][4], kl[4][4];
        #pragma unroll
        for (int np = 0; np < 4; ++np) {
            uint32_t boff = ((np * 16 + lr16) * SROWH + ks * 16 + lk8) * 2;
            ldsm4(kh[np], sb + 2 * 64 * SROWH * 2 + boff);
            ldsm4(kl[np], sb + 3 * 64 * SROWH * 2 + boff);
        }
        #pragma unroll
        for (int nf = 0; nf < 8; ++nf) {
            int np = nf >> 1, sub = nf & 1;
            mma16816(acc[nf], ah, kh[np][sub], kh[np][sub + 2]);
            mma16816(acc[nf], ah, kl[np][sub], kl[np][sub + 2]);
            mma16816(acc[nf], al, kh[np][sub], kh[np][sub + 2]);
        }
    }

    float* W = wei + (size_t)bh * Tt * Tt;
    const int erow = lane >> 2, ecol = (lane & 3) << 1;
    #pragma unroll
    for (int nf = 0; nf < 8; ++nf) {
        int col = col0 + nf * 8 + ecol;
        #pragma unroll
        for (int half = 0; half < 2; ++half) {
            int r = row0 + m0 + erow + half * 8;
            float2 o;
            o.x = (col     <= r) ? acc[nf][half * 2 + 0] * 0.125f : -INFINITY;
            o.y = (col + 1 <= r) ? acc[nf][half * 2 + 1] * 0.125f : -INFINITY;
            *(float2*)&W[(size_t)r * Tt + col] = o;
        }
    }
}

// ---------------- softmax over causal prefix, emits bf16 hi/lo P ----------------
__global__ void softmax_split_k(const float* __restrict__ wei,
                                bf16* __restrict__ phi, bf16* __restrict__ plo) {
    __shared__ float buf[256];
    int tid = threadIdx.x;
    int rowT = blockIdx.x & (Tt - 1);
    int cmax = ((rowT >> 6) + 1) << 6;          // end of diagonal tile
    const float* W = wei + (size_t)blockIdx.x * Tt;
    bool act = tid * 4 < cmax;
    float4 v = make_float4(-INFINITY, -INFINITY, -INFINITY, -INFINITY);
    if (act) v = ((const float4*)W)[tid];
    float m = fmaxf(fmaxf(v.x, v.y), fmaxf(v.z, v.w));
    m = block_reduce(m, buf, true);
    float4 e = make_float4(0.f, 0.f, 0.f, 0.f);
    if (act) {
        e.x = expf(v.x - m); e.y = expf(v.y - m);
        e.z = expf(v.z - m); e.w = expf(v.w - m);
    }
    float s = e.x + e.y + e.z + e.w;
    s = block_reduce(s, buf, false);
    float inv = 1.0f / s;
    if (act) {
        e.x *= inv; e.y *= inv; e.z *= inv; e.w *= inv;
        bf16 h0,l0,h1,l1,h2,l2,h3,l3;
        split2(e.x,h0,l0); split2(e.y,h1,l1); split2(e.z,h2,l2); split2(e.w,h3,l3);
        uint2 wh, wl;
        wh.x = packbf(h0,h1); wh.y = packbf(h2,h3);
        wl.x = packbf(l0,l1); wl.y = packbf(l2,l3);
        ((uint2*)(phi + (size_t)blockIdx.x * Tt))[tid] = wh;
        ((uint2*)(plo + (size_t)blockIdx.x * Tt))[tid] = wl;
    }
}

// ---------------- AV (bf16x3 MMA): att = P @ V, split bf16 out ----------------
// block 128 thr (4 warps), tile 64 rows x 64 (HS), BK=32, causal k-limit.
#define PROWH 40
#define VROWH 72
__global__ void __launch_bounds__(128) attn_av_mma(
    const bf16* __restrict__ phi, const bf16* __restrict__ plo,
    const bf16* __restrict__ qkvhi, const bf16* __restrict__ qkvlo,
    bf16* __restrict__ atthi, bf16* __restrict__ attlo)
{
    int bh = blockIdx.y;
    int b = bh >> 4, h = bh & 15;
    int row0 = blockIdx.x * 64;
    __shared__ bf16 sp[2][64][PROWH];
    __shared__ bf16 sv[2][32][VROWH];
    int tid = threadIdx.x, lane = tid & 31, warp = tid >> 5;
    const bf16* Ph = phi + (size_t)bh * Tt * Tt;
    const bf16* Pl = plo + (size_t)bh * Tt * Tt;
    const size_t vbase = (size_t)b * Tt * 3072 + 2048 + h * 64;

    const int NC = (row0 + 64) / 32;
    float acc[8][4];
    #pragma unroll
    for (int i = 0; i < 8; ++i)
        #pragma unroll
        for (int q = 0; q < 4; ++q) acc[i][q] = 0.f;

    // chunk-0 load
    #pragma unroll
    for (int p = 0; p < 8; ++p) {
        int arr = p >> 1;
        int idx = tid + (p & 1) * 128;     // 0..255
        if (arr < 2) {
            int r = idx >> 2, c8 = (idx & 3) * 8;
            const bf16* src = (arr == 0) ? Ph : Pl;
            *(uint4*)&sp[arr][r][c8] = *(const uint4*)(src + (size_t)(row0 + r) * Tt + c8);
        } else {
            int r = idx >> 3, c8 = (idx & 7) * 8;
            const bf16* src = (arr == 2) ? qkvhi : qkvlo;
            *(uint4*)&sv[arr - 2][r][c8] = *(const uint4*)(src + vbase + (size_t)r * 3072 + c8);
        }
    }
    __syncthreads();

    const uint32_t spb = smem_u32(sp);
    const uint32_t svb = smem_u32(sv);
    const int m0 = warp * 16;
    const int lr16 = lane & 15, lk8 = (lane >> 4) << 3;

    uint4 vreg[8];
    for (int c = 0; c < NC; ++c) {
        if (c + 1 < NC) {
            int k0 = (c + 1) * 32;
            #pragma unroll
            for (int p = 0; p < 8; ++p) {
                int arr = p >> 1;
                int idx = tid + (p & 1) * 128;
                if (arr < 2) {
                    int r = idx >> 2, c8 = (idx & 3) * 8;
                    const bf16* src = (arr == 0) ? Ph : Pl;
                    vreg[p] = *(const uint4*)(src + (size_t)(row0 + r) * Tt + k0 + c8);
                } else {
                    int r = idx >> 3, c8 = (idx & 7) * 8;
                    const bf16* src = (arr == 2) ? qkvhi : qkvlo;
                    vreg[p] = *(const uint4*)(src + vbase + (size_t)(k0 + r) * 3072 + c8);
                }
            }
        }

        #pragma unroll
        for (int ks = 0; ks < 2; ++ks) {
            uint32_t ph4[4], pl4[4];
            uint32_t aoff = ((m0 + lr16) * PROWH + ks * 16 + lk8) * 2;
            ldsm4(ph4, spb + aoff);
            ldsm4(pl4, spb + 64 * PROWH * 2 + aoff);
            uint32_t vh[4][4], vl[4][4];
            #pragma unroll
            for (int np = 0; np < 4; ++np) {
                uint32_t boff = ((ks * 16 + lr16) * VROWH + np * 16 + lk8) * 2;
                ldsm4t(vh[np], svb + boff);
                ldsm4t(vl[np], svb + 32 * VROWH * 2 + boff);
            }
            #pragma unroll
            for (int nf = 0; nf < 8; ++nf) {
                int np = nf >> 1, sub = nf & 1;
                mma16816(acc[nf], ph4, vh[np][sub * 2], vh[np][sub * 2 + 1]);
                mma16816(acc[nf], ph4, vl[np][sub * 2], vl[np][sub * 2 + 1]);
                mma16816(acc[nf], pl4, vh[np][sub * 2], vh[np][sub * 2 + 1]);
            }
        }

        if (c + 1 < NC) {
            __syncthreads();
            #pragma unroll
            for (int p = 0; p < 8; ++p) {
                int arr = p >> 1;
                int idx = tid + (p & 1) * 128;
                if (arr < 2) {
                    int r = idx >> 2, c8 = (idx & 3) * 8;
                    *(uint4*)&sp[arr][r][c8] = vreg[p];
                } else {
                    int r = idx >> 3, c8 = (idx & 7) * 8;
                    *(uint4*)&sv[arr - 2][r][c8] = vreg[p];
                }
            }
            __syncthreads();
        }
    }

    const int erow = lane >> 2, ecol = (lane & 3) << 1;
    #pragma unroll
    for (int nf = 0; nf < 8; ++nf) {
        int col = h * 64 + nf * 8 + ecol;
        #pragma unroll
        for (int half = 0; half < 2; ++half) {
            int r = (size_t)b * Tt + row0 + m0 + erow + half * 8;
            float ox = acc[nf][half * 2 + 0];
            float oy = acc[nf][half * 2 + 1];
            bf16 h0,l0,h1,l1;
            split2(ox,h0,l0); split2(oy,h1,l1);
            *(uint32_t*)&atthi[(size_t)r * Cc + col] = packbf(h0,h1);
            *(uint32_t*)&attlo[(size_t)r * Cc + col] = packbf(l0,l1);
        }
    }
}

// ---------------- loss ----------------
__global__ void loss_rows_k(const float* __restrict__ logits, const int* __restrict__ targets,
                            float* __restrict__ rowloss) {
    __shared__ float buf[256];
    const float* L = logits + (size_t)blockIdx.x * Vv;
    int tid = threadIdx.x;
    const int V4 = Vv / 4;
    float m = -INFINITY;
    for (int j = tid; j < V4; j += 256) {
        float4 v = ((const float4*)L)[j];
        m = fmaxf(m, fmaxf(fmaxf(v.x, v.y), fmaxf(v.z, v.w)));
    }
    m = block_reduce(m, buf, true);
    float s = 0.f;
    for (int j = tid; j < V4; j += 256) {
        float4 v = ((const float4*)L)[j];
        s += expf(v.x - m) + expf(v.y - m) + expf(v.z - m) + expf(v.w - m);
    }
    s = block_reduce(s, buf, false);
    if (tid == 0) rowloss[blockIdx.x] = logf(s) + m - L[targets[blockIdx.x]];
}

__global__ void loss_reduce_k(const float* __restrict__ rowloss, float* __restrict__ out) {
    __shared__ float buf[256];
    int tid = threadIdx.x;
    float s = 0.f;
    for (int j = tid; j < Mm; j += 256) s += rowloss[j];
    s = block_reduce(s, buf, false);
    if (tid == 0) out[0] = s / (float)Mm;
}

// ---------------- launch ----------------
extern "C" void kernel_launch(void* const* d_in, const int* in_sizes, int n_in,
                              void* d_out, int out_size)
{
    const int*   idx     = (const int*)d_in[0];
    const int*   targets = (const int*)d_in[1];
    const float* tok_emb = (const float*)d_in[2];
    const float* pos_emb = (const float*)d_in[3];
    const float* ln1_g   = (const float*)d_in[4];
    const float* ln1_b   = (const float*)d_in[5];
    const float* Wq      = (const float*)d_in[6];
    const float* Wk      = (const float*)d_in[7];
    const float* Wv      = (const float*)d_in[8];
    const float* Wo      = (const float*)d_in[9];
    const float* bo      = (const float*)d_in[10];
    const float* ln2_g   = (const float*)d_in[11];
    const float* ln2_b   = (const float*)d_in[12];
    const float* W1      = (const float*)d_in[13];
    const float* b1      = (const float*)d_in[14];
    const float* W2      = (const float*)d_in[15];
    const float* b2      = (const float*)d_in[16];
    const float* lnf_g   = (const float*)d_in[17];
    const float* lnf_b   = (const float*)d_in[18];
    const float* Wlm     = (const float*)d_in[19];
    const float* blm     = (const float*)d_in[20];
    float* out = (float*)d_out;

    float *px, *pwei, *prl;
    bf16 *phhi, *phlo, *pqkvhi, *pqkvlo, *pphi, *pplo, *patthi, *pattlo,
         *pffhi, *pfflo, *pwhi, *pwlo;
    cudaGetSymbolAddress((void**)&px,     g_x);
    cudaGetSymbolAddress((void**)&pwei,   g_wei);
    cudaGetSymbolAddress((void**)&prl,    g_rowloss);
    cudaGetSymbolAddress((void**)&phhi,   g_hhi);
    cudaGetSymbolAddress((void**)&phlo,   g_hlo);
    cudaGetSymbolAddress((void**)&pqkvhi, g_qkvhi);
    cudaGetSymbolAddress((void**)&pqkvlo, g_qkvlo);
    cudaGetSymbolAddress((void**)&pphi,   g_phi);
    cudaGetSymbolAddress((void**)&pplo,   g_plo);
    cudaGetSymbolAddress((void**)&patthi, g_atthi);
    cudaGetSymbolAddress((void**)&pattlo, g_attlo);
    cudaGetSymbolAddress((void**)&pffhi,  g_ffhhi);
    cudaGetSymbolAddress((void**)&pfflo,  g_ffhlo);
    cudaGetSymbolAddress((void**)&pwhi,   g_whi);
    cudaGetSymbolAddress((void**)&pwlo,   g_wlo);

    cudaFuncSetAttribute(gemm_tc<true,false,false,false>, cudaFuncAttributeMaxDynamicSharedMemorySize, GEMM_SMEM);
    cudaFuncSetAttribute(gemm_tc<false,true,true,false>,  cudaFuncAttributeMaxDynamicSharedMemorySize, GEMM_SMEM);
    cudaFuncSetAttribute(gemm_tc<true,true,false,true>,   cudaFuncAttributeMaxDynamicSharedMemorySize, GEMM_SMEM);
    cudaFuncSetAttribute(gemm_tc<false,true,false,false>, cudaFuncAttributeMaxDynamicSharedMemorySize, GEMM_SMEM);

    embed_k<<<(Mm * Cc / 4 + 255) / 256, 256>>>(idx, tok_emb, pos_emb, px);

    dim3 gQKV(3072 / 128, Mm / 128);    // 24 x 32
    dim3 gC(Cc / 128, Mm / 128);        // 8 x 32
    dim3 gF(FFd / 128, Mm / 128);       // 32 x 32
    dim3 gVh(Vv / 128, Mm / 128);       // 393 x 32
    dim3 gS(Tt / 64, Tt / 64, Bb * Hh);
    dim3 gA(Tt / 64, Bb * Hh);

    for (int l = 0; l < Ll; ++l) {
        const size_t oCC = (size_t)l * Cc * Cc;
        const size_t oC  = (size_t)l * Cc;
        const size_t oCF = (size_t)l * Cc * FFd;
        const size_t oF  = (size_t)l * FFd;

        layernorm_split_k<<<Mm, 256>>>(px, ln1_g + oC, ln1_b + oC, phhi, phlo);
        conv_wT_k<<<dim3(Cc / 32, Cc / 32), 256>>>(Wq + oCC, Cc, Cc, 0,    pwhi, pwlo);
        conv_wT_k<<<dim3(Cc / 32, Cc / 32), 256>>>(Wk + oCC, Cc, Cc, 1024, pwhi, pwlo);
        conv_wT_k<<<dim3(Cc / 32, Cc / 32), 256>>>(Wv + oCC, Cc, Cc, 2048, pwhi, pwlo);
        gemm_tc<true,false,false,false><<<gQKV, 256, GEMM_SMEM>>>(
            Cc, phhi, phlo, pwhi, pwlo, nullptr, nullptr, 0,
            nullptr, pqkvhi, pqkvlo, 3072);

        attn_scores_mma<<<gS, 128>>>(pqkvhi, pqkvlo, pwei);
        softmax_split_k<<<Bb * Hh * Tt, 256>>>(pwei, pphi, pplo);
        attn_av_mma<<<gA, 128>>>(pphi, pplo, pqkvhi, pqkvlo, patthi, pattlo);

        conv_wT_k<<<dim3(Cc / 32, Cc / 32), 256>>>(Wo + oCC, Cc, Cc, 0, pwhi, pwlo);
        gemm_tc<false,true,true,false><<<gC, 256, GEMM_SMEM>>>(
            Cc, patthi, pattlo, pwhi, pwlo, bo + oC, px, Cc,
            px, nullptr, nullptr, Cc);

        layernorm_split_k<<<Mm, 256>>>(px, ln2_g + oC, ln2_b + oC, phhi, phlo);
        conv_wT_k<<<dim3(FFd / 32, Cc / 32), 256>>>(W1 + oCF, Cc, FFd, 0, pwhi, pwlo);
        gemm_tc<true,true,false,true><<<gF, 256, GEMM_SMEM>>>(
            Cc, phhi, phlo, pwhi, pwlo, b1 + oF, nullptr, 0,
            nullptr, pffhi, pfflo, FFd);

        conv_wT_k<<<dim3(Cc / 32, FFd / 32), 256>>>(W2 + oCF, FFd, Cc, 0, pwhi, pwlo);
        gemm_tc<false,true,true,false><<<gC, 256, GEMM_SMEM>>>(
            FFd, pffhi, pfflo, pwhi, pwlo, b2 + oC, px, Cc,
            px, nullptr, nullptr, Cc);
    }

    // final LN + LM head -> logits into d_out
    layernorm_split_k<<<Mm, 256>>>(px, lnf_g, lnf_b, phhi, phlo);
    conv_wT_k<<<dim3(Vv / 32, Cc / 32), 256>>>(Wlm, Cc, Vv, 0, pwhi, pwlo);
    gemm_tc<false,true,false,false><<<gVh, 256, GEMM_SMEM>>>(
        Cc, phhi, phlo, pwhi, pwlo, blm, nullptr, 0,
        out, nullptr, nullptr, Vv);

    long long logitsN = (long long)Mm * Vv;
    if ((long long)out_size > logitsN) {
        loss_rows_k<<<Mm, 256>>>(out, targets, prl);
        loss_reduce_k<<<1, 256>>>(prl, out + logitsN);
    }
}

// round 9
// speedup vs baseline: 2.1668x; 1.0514x over previous
#include <cuda_runtime.h>
#include <cuda_bf16.h>
#include <math.h>
#include <stdint.h>

// Problem constants
#define Bb 4
#define Tt 1024
#define Cc 1024
#define Hh 16
#define HSs 64
#define Ll 12
#define Vv 50304
#define Mm (Bb*Tt)      // 4096
#define FFd (4*Cc)      // 4096

typedef __nv_bfloat16 bf16;

// ---------------- scratch (static device memory; no allocations) ----------------
__device__ float g_x[(size_t)Mm*Cc];
__device__ float g_rowloss[Mm];
__device__ bf16 g_hhi[(size_t)Mm*Cc];
__device__ bf16 g_hlo[(size_t)Mm*Cc];
__device__ bf16 g_qkvhi[(size_t)Mm*3072];
__device__ bf16 g_qkvlo[(size_t)Mm*3072];
__device__ bf16 g_atthi[(size_t)Mm*Cc];
__device__ bf16 g_attlo[(size_t)Mm*Cc];
__device__ bf16 g_ffhhi[(size_t)Mm*FFd];
__device__ bf16 g_ffhlo[(size_t)Mm*FFd];
__device__ bf16 g_whi[(size_t)Vv*Cc];
__device__ bf16 g_wlo[(size_t)Vv*Cc];

// ---------------- PTX helpers (portable, no arch-a gating) ----------------
__device__ __forceinline__ uint32_t smem_u32(const void* p) {
    uint32_t a;
    asm("{ .reg .u64 t; cvta.to.shared.u64 t, %1; cvt.u32.u64 %0, t; }" : "=r"(a) : "l"(p));
    return a;
}
__device__ __forceinline__ void ldsm4(uint32_t* r, uint32_t a) {
    asm volatile("ldmatrix.sync.aligned.m8n8.x4.shared.b16 {%0,%1,%2,%3}, [%4];"
        : "=r"(r[0]), "=r"(r[1]), "=r"(r[2]), "=r"(r[3]) : "r"(a));
}
__device__ __forceinline__ void ldsm4t(uint32_t* r, uint32_t a) {
    asm volatile("ldmatrix.sync.aligned.m8n8.x4.trans.shared.b16 {%0,%1,%2,%3}, [%4];"
        : "=r"(r[0]), "=r"(r[1]), "=r"(r[2]), "=r"(r[3]) : "r"(a));
}
__device__ __forceinline__ void mma16816(float* c, const uint32_t* a, uint32_t b0, uint32_t b1) {
    asm volatile("mma.sync.aligned.m16n8k16.row.col.f32.bf16.bf16.f32 "
        "{%0,%1,%2,%3}, {%4,%5,%6,%7}, {%8,%9}, {%0,%1,%2,%3};"
        : "+f"(c[0]), "+f"(c[1]), "+f"(c[2]), "+f"(c[3])
        : "r"(a[0]), "r"(a[1]), "r"(a[2]), "r"(a[3]), "r"(b0), "r"(b1));
}
__device__ __forceinline__ void cpa16(uint32_t saddr, const void* g) {
    asm volatile("cp.async.cg.shared.global [%0], [%1], 16;" :: "r"(saddr), "l"(g));
}
#define CPCOMMIT() asm volatile("cp.async.commit_group;" ::: "memory")
#define CPWAIT1()  asm volatile("cp.async.wait_group 1;" ::: "memory")
#define CPWAIT0()  asm volatile("cp.async.wait_group 0;" ::: "memory")

__device__ __forceinline__ float ex2f(float x) {
    float y; asm("ex2.approx.f32 %0, %1;" : "=f"(y) : "f"(x)); return y;
}
__device__ __forceinline__ void split2(float x, bf16& h, bf16& l) {
    h = __float2bfloat16(x);
    l = __float2bfloat16(x - __bfloat162float(h));
}
__device__ __forceinline__ uint32_t packbf(bf16 a, bf16 b) {
    return (uint32_t)__bfloat16_as_ushort(a) | ((uint32_t)__bfloat16_as_ushort(b) << 16);
}
__device__ __forceinline__ uint32_t splitpack(float x0, float x1, uint32_t& lo) {
    bf16 h0,l0,h1,l1;
    split2(x0,h0,l0); split2(x1,h1,l1);
    lo = packbf(l0,l1);
    return packbf(h0,h1);
}

// ---------------- helpers ----------------
__device__ __forceinline__ float block_reduce(float v, float* buf, bool ismax) {
    int tid = threadIdx.x;            // blockDim.x == 256
    buf[tid] = v;
    __syncthreads();
    #pragma unroll
    for (int s = 128; s > 0; s >>= 1) {
        if (tid < s) buf[tid] = ismax ? fmaxf(buf[tid], buf[tid + s]) : (buf[tid] + buf[tid + s]);
        __syncthreads();
    }
    float r = buf[0];
    __syncthreads();
    return r;
}

// ---------------- embed ----------------
__global__ void embed_k(const int* __restrict__ idx, const float* __restrict__ tok,
                        const float* __restrict__ pos, float* __restrict__ x) {
    int i4 = blockIdx.x * blockDim.x + threadIdx.x;
    if (i4 >= Mm * Cc / 4) return;
    int c  = (i4 % (Cc / 4)) * 4;
    int bt = i4 / (Cc / 4);
    int t  = bt % Tt;
    int tk = idx[bt];
    float4 a = *(const float4*)&tok[(size_t)tk * Cc + c];
    float4 p = *(const float4*)&pos[(size_t)t * Cc + c];
    a.x += p.x; a.y += p.y; a.z += p.z; a.w += p.w;
    *(float4*)&x[(size_t)bt * Cc + c] = a;
}

// ---------------- layernorm: fp32 in, bf16 hi/lo out ----------------
__global__ void layernorm_split_k(const float* __restrict__ x, const float* __restrict__ g,
                                  const float* __restrict__ b,
                                  bf16* __restrict__ yhi, bf16* __restrict__ ylo) {
    __shared__ float buf[256];
    int tid = threadIdx.x;
    const float* xr = x + (size_t)blockIdx.x * Cc;
    float4 v = ((const float4*)xr)[tid];
    float s  = v.x + v.y + v.z + v.w;
    float sq = v.x*v.x + v.y*v.y + v.z*v.z + v.w*v.w;
    s  = block_reduce(s,  buf, false);
    sq = block_reduce(sq, buf, false);
    float mean = s * (1.0f / Cc);
    float var  = sq * (1.0f / Cc) - mean * mean;
    float r    = rsqrtf(var + 1e-5f);
    float4 gg = ((const float4*)g)[tid];
    float4 bb = ((const float4*)b)[tid];
    float o0 = (v.x - mean) * r * gg.x + bb.x;
    float o1 = (v.y - mean) * r * gg.y + bb.y;
    float o2 = (v.z - mean) * r * gg.z + bb.z;
    float o3 = (v.w - mean) * r * gg.w + bb.w;
    uint2 wh, wl;
    wh.x = splitpack(o0, o1, wl.x);
    wh.y = splitpack(o2, o3, wl.y);
    ((uint2*)(yhi + (size_t)blockIdx.x * Cc))[tid] = wh;
    ((uint2*)(ylo + (size_t)blockIdx.x * Cc))[tid] = wl;
}

// ---------------- W [K,N] fp32 -> transposed [N,K] bf16 hi/lo at row offset ----------------
__global__ void conv_wT_k(const float* __restrict__ W, int K, int N, int n_off,
                          bf16* __restrict__ hi, bf16* __restrict__ lo) {
    __shared__ float t[32][33];
    int n0 = blockIdx.x * 32, k0 = blockIdx.y * 32;
    int tx = threadIdx.x & 31, ty = threadIdx.x >> 5;   // 256 threads: 32 x 8
    #pragma unroll
    for (int i = 0; i < 32; i += 8)
        t[ty + i][tx] = W[(size_t)(k0 + ty + i) * N + n0 + tx];
    __syncthreads();
    #pragma unroll
    for (int i = 0; i < 32; i += 8) {
        int n = ty + i;
        float x = t[tx][n];                          // W[k0+tx][n0+n]
        bf16 h, l;
        split2(x, h, l);
        hi[(size_t)(n_off + n0 + n) * K + k0 + tx] = h;
        lo[(size_t)(n_off + n0 + n) * K + k0 + tx] = l;
    }
}

// QKV weights: 3 convs in one launch (z selects the matrix)
__global__ void conv_wqkv_k(const float* __restrict__ Wq, const float* __restrict__ Wk,
                            const float* __restrict__ Wv,
                            bf16* __restrict__ hi, bf16* __restrict__ lo) {
    __shared__ float t[32][33];
    const float* W = (blockIdx.z == 0) ? Wq : (blockIdx.z == 1) ? Wk : Wv;
    int n_off = blockIdx.z * 1024;
    int n0 = blockIdx.x * 32, k0 = blockIdx.y * 32;
    int tx = threadIdx.x & 31, ty = threadIdx.x >> 5;
    #pragma unroll
    for (int i = 0; i < 32; i += 8)
        t[ty + i][tx] = W[(size_t)(k0 + ty + i) * Cc + n0 + tx];
    __syncthreads();
    #pragma unroll
    for (int i = 0; i < 32; i += 8) {
        int n = ty + i;
        float x = t[tx][n];
        bf16 h, l;
        split2(x, h, l);
        hi[(size_t)(n_off + n0 + n) * Cc + k0 + tx] = h;
        lo[(size_t)(n_off + n0 + n) * Cc + k0 + tx] = l;
    }
}

// ---------------- bf16x3 tensor-core GEMM, cp.async 3-stage pipeline ----------------
#define BKh      32
#define ROWH     40
#define ARR_B    (128 * ROWH * 2)      // 10240 B
#define STAGE_B  (4 * ARR_B)           // 40960 B
#define GEMM_SMEM (3 * STAGE_B)        // 122880 B

__device__ __forceinline__ void issue_stage(
    uint32_t sbase, int buf, int tid, int rowBase, int colBase, int K, int k0,
    const bf16* __restrict__ Ahi, const bf16* __restrict__ Alo,
    const bf16* __restrict__ Bhi, const bf16* __restrict__ Blo)
{
    const int lrow = tid >> 2;
    const int lc8  = (tid & 3) << 3;
    uint32_t sb = sbase + (uint32_t)buf * STAGE_B;
    #pragma unroll
    for (int p = 0; p < 8; ++p) {
        int arr = p >> 1;
        int row = ((p & 1) << 6) + lrow;
        const bf16* src = (arr == 0) ? Ahi : (arr == 1) ? Alo : (arr == 2) ? Bhi : Blo;
        int rb = (arr < 2) ? rowBase : colBase;
        cpa16(sb + arr * ARR_B + (row * ROWH + lc8) * 2,
              src + (size_t)(rb + row) * K + k0 + lc8);
    }
}

template<bool SPLIT, bool BIAS, bool RES, bool RELU>
__global__ void __launch_bounds__(256) gemm_tc(
    int K,
    const bf16* __restrict__ Ahi, const bf16* __restrict__ Alo,
    const bf16* __restrict__ Bhi, const bf16* __restrict__ Blo,
    const float* __restrict__ bias, const float* __restrict__ res, int ldr,
    float* __restrict__ C, bf16* __restrict__ Chi, bf16* __restrict__ Clo, int ldc)
{
    extern __shared__ __align__(16) char smem[];
    const uint32_t sbase = smem_u32(smem);
    const int tid  = threadIdx.x;
    const int lane = tid & 31;
    const int warp = tid >> 5;
    const int m0 = (warp & 1) * 64, n0 = (warp >> 1) * 32;
    const int rowBase = blockIdx.y * 128;
    const int colBase = blockIdx.x * 128;

    float acc[4][4][4];
    #pragma unroll
    for (int i = 0; i < 4; ++i)
        #pragma unroll
        for (int j = 0; j < 4; ++j)
            #pragma unroll
            for (int q = 0; q < 4; ++q) acc[i][j][q] = 0.f;

    const int NC = K / BKh;

    issue_stage(sbase, 0, tid, rowBase, colBase, K, 0, Ahi, Alo, Bhi, Blo);
    CPCOMMIT();
    issue_stage(sbase, 1, tid, rowBase, colBase, K, BKh, Ahi, Alo, Bhi, Blo);
    CPCOMMIT();

    const int lr16 = lane & 15;
    const int lk8  = (lane >> 4) << 3;
    int buf = 0, nbuf = 2;

    for (int c = 0; c < NC; ++c) {
        if (c + 1 < NC) { CPWAIT1(); } else { CPWAIT0(); }
        __syncthreads();
        if (c + 2 < NC) {
            issue_stage(sbase, nbuf, tid, rowBase, colBase, K, (c + 2) * BKh, Ahi, Alo, Bhi, Blo);
            CPCOMMIT();
            nbuf = (nbuf + 1 == 3) ? 0 : nbuf + 1;
        }
        const uint32_t st = sbase + (uint32_t)buf * STAGE_B;
        buf = (buf + 1 == 3) ? 0 : buf + 1;

        #pragma unroll
        for (int ks = 0; ks < 2; ++ks) {
            uint32_t bh[2][4], bl[2][4];
            #pragma unroll
            for (int np = 0; np < 2; ++np) {
                uint32_t off = ((n0 + np * 16 + lr16) * ROWH + ks * 16 + lk8) * 2;
                ldsm4(bh[np], st + 2 * ARR_B + off);
                ldsm4(bl[np], st + 3 * ARR_B + off);
            }
            uint32_t ah[4][4], av[4][4];
            #pragma unroll
            for (int mf = 0; mf < 4; ++mf) {
                uint32_t off = ((m0 + mf * 16 + lr16) * ROWH + ks * 16 + lk8) * 2;
                ldsm4(ah[mf], st + off);
                ldsm4(av[mf], st + ARR_B + off);
            }
            // term-major ordering: same-acc reuse distance = 16 MMAs
            #pragma unroll
            for (int mf = 0; mf < 4; ++mf)
                #pragma unroll
                for (int nf = 0; nf < 4; ++nf) {
                    int np = nf >> 1, sub = nf & 1;
                    mma16816(acc[mf][nf], ah[mf], bh[np][sub], bh[np][sub + 2]);
                }
            #pragma unroll
            for (int mf = 0; mf < 4; ++mf)
                #pragma unroll
                for (int nf = 0; nf < 4; ++nf) {
                    int np = nf >> 1, sub = nf & 1;
                    mma16816(acc[mf][nf], ah[mf], bl[np][sub], bl[np][sub + 2]);
                }
            #pragma unroll
            for (int mf = 0; mf < 4; ++mf)
                #pragma unroll
                for (int nf = 0; nf < 4; ++nf) {
                    int np = nf >> 1, sub = nf & 1;
                    mma16816(acc[mf][nf], av[mf], bh[np][sub], bh[np][sub + 2]);
                }
        }
        __syncthreads();
    }

    const int erow = lane >> 2;
    const int ecol = (lane & 3) << 1;
    #pragma unroll
    for (int mf = 0; mf < 4; ++mf) {
        #pragma unroll
        for (int nf = 0; nf < 4; ++nf) {
            int row = rowBase + m0 + mf * 16 + erow;
            int col = colBase + n0 + nf * 8 + ecol;
            #pragma unroll
            for (int half = 0; half < 2; ++half) {
                int r = row + half * 8;
                float ox = acc[mf][nf][half * 2 + 0];
                float oy = acc[mf][nf][half * 2 + 1];
                if (BIAS) {
                    float2 bv = *(const float2*)&bias[col];
                    ox += bv.x; oy += bv.y;
                }
                if (RES) {
                    float2 rv = *(const float2*)&res[(size_t)r * ldr + col];
                    ox += rv.x; oy += rv.y;
                }
                if (RELU) { ox = fmaxf(ox, 0.f); oy = fmaxf(oy, 0.f); }
                if (SPLIT) {
                    uint32_t wl;
                    uint32_t wh = splitpack(ox, oy, wl);
                    *(uint32_t*)&Chi[(size_t)r * ldc + col] = wh;
                    *(uint32_t*)&Clo[(size_t)r * ldc + col] = wl;
                } else {
                    float2 o; o.x = ox; o.y = oy;
                    *(float2*)&C[(size_t)r * ldc + col] = o;
                }
            }
        }
    }
}

// ---------------- fused flash attention (bf16x3 MMA, online softmax) ----------------
// grid (T/64, B*H), 128 threads (4 warps, 16 rows each). Q tile 64x64 resident;
// iterate K/V tiles of 64. P stays in registers (acc layout == A-frag layout).
#define AROWH 72
#define FA_Q0 0
#define FA_Q1 9216
#define FA_K0 18432
#define FA_K1 27648
#define FA_V0 36864
#define FA_V1 46080
#define FA_SMEM 55296

__global__ void __launch_bounds__(128, 2) flash_attn_k(
    const bf16* __restrict__ qkvhi, const bf16* __restrict__ qkvlo,
    bf16* __restrict__ atthi, bf16* __restrict__ attlo)
{
    extern __shared__ __align__(16) char fsm[];
    const uint32_t sb = smem_u32(fsm);
    const int tid = threadIdx.x, lane = tid & 31, warp = tid >> 5;
    const int bh = blockIdx.y;
    const int b = bh >> 4, h = bh & 15;
    const int row0 = blockIdx.x * 64;
    const size_t qbase = (size_t)b * Tt * 3072 + h * 64;
    const size_t kbase = qbase + 1024;
    const size_t vbase = qbase + 2048;

    // load Q tile (hi/lo) once
    #pragma unroll
    for (int p = 0; p < 4; ++p) {
        int idx = tid + p * 128;
        int r = idx >> 3, c8 = (idx & 7) * 8;
        *(uint4*)(fsm + FA_Q0 + (r * AROWH + c8) * 2) =
            *(const uint4*)(qkvhi + qbase + (size_t)(row0 + r) * 3072 + c8);
        *(uint4*)(fsm + FA_Q1 + (r * AROWH + c8) * 2) =
            *(const uint4*)(qkvlo + qbase + (size_t)(row0 + r) * 3072 + c8);
    }

    const int m0 = warp * 16;
    const int lr16 = lane & 15, lk8 = (lane >> 4) << 3;
    const int g = lane >> 2;
    const int ec = (lane & 3) << 1;
    const float SCL = 0.125f * 1.4426950408889634f;   // to log2 domain

    float m_[2] = { -INFINITY, -INFINITY };
    float l_[2] = { 0.f, 0.f };
    float oacc[8][4];
    #pragma unroll
    for (int i = 0; i < 8; ++i)
        #pragma unroll
        for (int q = 0; q < 4; ++q) oacc[i][q] = 0.f;

    for (int j0 = 0; j0 <= row0; j0 += 64) {
        __syncthreads();
        #pragma unroll
        for (int p = 0; p < 4; ++p) {
            int idx = tid + p * 128;
            int r = idx >> 3, c8 = (idx & 7) * 8;
            *(uint4*)(fsm + FA_K0 + (r * AROWH + c8) * 2) =
                *(const uint4*)(qkvhi + kbase + (size_t)(j0 + r) * 3072 + c8);
            *(uint4*)(fsm + FA_K1 + (r * AROWH + c8) * 2) =
                *(const uint4*)(qkvlo + kbase + (size_t)(j0 + r) * 3072 + c8);
            *(uint4*)(fsm + FA_V0 + (r * AROWH + c8) * 2) =
                *(const uint4*)(qkvhi + vbase + (size_t)(j0 + r) * 3072 + c8);
            *(uint4*)(fsm + FA_V1 + (r * AROWH + c8) * 2) =
                *(const uint4*)(qkvlo + vbase + (size_t)(j0 + r) * 3072 + c8);
        }
        __syncthreads();

        // S = Q K^T (3-term)
        float sacc[8][4];
        #pragma unroll
        for (int i = 0; i < 8; ++i)
            #pragma unroll
            for (int q = 0; q < 4; ++q) sacc[i][q] = 0.f;

        #pragma unroll
        for (int ks = 0; ks < 4; ++ks) {
            uint32_t ah[4], al[4];
            uint32_t aoff = ((m0 + lr16) * AROWH + ks * 16 + lk8) * 2;
            ldsm4(ah, sb + FA_Q0 + aoff);
            ldsm4(al, sb + FA_Q1 + aoff);
            uint32_t kh[4][4], kl[4][4];
            #pragma unroll
            for (int np = 0; np < 4; ++np) {
                uint32_t boff = ((np * 16 + lr16) * AROWH + ks * 16 + lk8) * 2;
                ldsm4(kh[np], sb + FA_K0 + boff);
                ldsm4(kl[np], sb + FA_K1 + boff);
            }
            #pragma unroll
            for (int nf = 0; nf < 8; ++nf) {
                int np = nf >> 1, sub = nf & 1;
                mma16816(sacc[nf], ah, kh[np][sub], kh[np][sub + 2]);
            }
            #pragma unroll
            for (int nf = 0; nf < 8; ++nf) {
                int np = nf >> 1, sub = nf & 1;
                mma16816(sacc[nf], ah, kl[np][sub], kl[np][sub + 2]);
            }
            #pragma unroll
            for (int nf = 0; nf < 8; ++nf) {
                int np = nf >> 1, sub = nf & 1;
                mma16816(sacc[nf], al, kh[np][sub], kh[np][sub + 2]);
            }
        }

        // scale, mask (diagonal tile), row max
        const bool diag = (j0 == row0);
        float mx0 = -INFINITY, mx1 = -INFINITY;
        #pragma unroll
        for (int nf = 0; nf < 8; ++nf) {
            #pragma unroll
            for (int q = 0; q < 4; ++q) {
                float vsc = sacc[nf][q] * SCL;
                if (diag) {
                    int cc = nf * 8 + ec + (q & 1);
                    int rr = m0 + g + ((q >> 1) << 3);
                    if (cc > rr) vsc = -INFINITY;
                }
                sacc[nf][q] = vsc;
                if (q < 2) mx0 = fmaxf(mx0, vsc); else mx1 = fmaxf(mx1, vsc);
            }
        }
        mx0 = fmaxf(mx0, __shfl_xor_sync(0xffffffffu, mx0, 1));
        mx0 = fmaxf(mx0, __shfl_xor_sync(0xffffffffu, mx0, 2));
        mx1 = fmaxf(mx1, __shfl_xor_sync(0xffffffffu, mx1, 1));
        mx1 = fmaxf(mx1, __shfl_xor_sync(0xffffffffu, mx1, 2));

        float mn0 = fmaxf(m_[0], mx0), mn1 = fmaxf(m_[1], mx1);
        float a0 = ex2f(m_[0] - mn0), a1 = ex2f(m_[1] - mn1);
        m_[0] = mn0; m_[1] = mn1;

        float s0 = 0.f, s1 = 0.f;
        #pragma unroll
        for (int nf = 0; nf < 8; ++nf) {
            float p0 = ex2f(sacc[nf][0] - mn0);
            float p1 = ex2f(sacc[nf][1] - mn0);
            float p2 = ex2f(sacc[nf][2] - mn1);
            float p3 = ex2f(sacc[nf][3] - mn1);
            sacc[nf][0] = p0; sacc[nf][1] = p1; sacc[nf][2] = p2; sacc[nf][3] = p3;
            s0 += p0 + p1; s1 += p2 + p3;
        }
        l_[0] = l_[0] * a0 + s0;
        l_[1] = l_[1] * a1 + s1;
        #pragma unroll
        for (int nf = 0; nf < 8; ++nf) {
            oacc[nf][0] *= a0; oacc[nf][1] *= a0;
            oacc[nf][2] *= a1; oacc[nf][3] *= a1;
        }

        // pack P into A-fragments (acc layout == A-frag layout)
        uint32_t pah[4][4], pal[4][4];
        #pragma unroll
        for (int kf = 0; kf < 4; ++kf) {
            pah[kf][0] = splitpack(sacc[2*kf][0],   sacc[2*kf][1],   pal[kf][0]);
            pah[kf][1] = splitpack(sacc[2*kf][2],   sacc[2*kf][3],   pal[kf][1]);
            pah[kf][2] = splitpack(sacc[2*kf+1][0], sacc[2*kf+1][1], pal[kf][2]);
            pah[kf][3] = splitpack(sacc[2*kf+1][2], sacc[2*kf+1][3], pal[kf][3]);
        }

        // O += P @ V (3-term)
        #pragma unroll
        for (int kf = 0; kf < 4; ++kf) {
            uint32_t vh[4][4], vl[4][4];
            #pragma unroll
            for (int np = 0; np < 4; ++np) {
                uint32_t boff = ((kf * 16 + lr16) * AROWH + np * 16 + lk8) * 2;
                ldsm4t(vh[np], sb + FA_V0 + boff);
                ldsm4t(vl[np], sb + FA_V1 + boff);
            }
            #pragma unroll
            for (int nf = 0; nf < 8; ++nf) {
                int np = nf >> 1, sub = nf & 1;
                mma16816(oacc[nf], pah[kf], vh[np][sub * 2], vh[np][sub * 2 + 1]);
            }
            #pragma unroll
            for (int nf = 0; nf < 8; ++nf) {
                int np = nf >> 1, sub = nf & 1;
                mma16816(oacc[nf], pah[kf], vl[np][sub * 2], vl[np][sub * 2 + 1]);
            }
            #pragma unroll
            for (int nf = 0; nf < 8; ++nf) {
                int np = nf >> 1, sub = nf & 1;
                mma16816(oacc[nf], pal[kf], vh[np][sub * 2], vh[np][sub * 2 + 1]);
            }
        }
    }

    // finalize: divide by row sums (reduced over the 4-lane quad), split, write
    float l0 = l_[0], l1 = l_[1];
    l0 += __shfl_xor_sync(0xffffffffu, l0, 1);
    l0 += __shfl_xor_sync(0xffffffffu, l0, 2);
    l1 += __shfl_xor_sync(0xffffffffu, l1, 1);
    l1 += __shfl_xor_sync(0xffffffffu, l1, 2);
    float inv0 = 1.0f / l0, inv1 = 1.0f / l1;

    #pragma unroll
    for (int nf = 0; nf < 8; ++nf) {
        int col = h * 64 + nf * 8 + ec;
        size_t r0 = (size_t)b * Tt + row0 + m0 + g;
        uint32_t wl;
        uint32_t wh = splitpack(oacc[nf][0] * inv0, oacc[nf][1] * inv0, wl);
        *(uint32_t*)&atthi[r0 * Cc + col] = wh;
        *(uint32_t*)&attlo[r0 * Cc + col] = wl;
        wh = splitpack(oacc[nf][2] * inv1, oacc[nf][3] * inv1, wl);
        *(uint32_t*)&atthi[(r0 + 8) * Cc + col] = wh;
        *(uint32_t*)&attlo[(r0 + 8) * Cc + col] = wl;
    }
}

// ---------------- loss ----------------
__global__ void loss_rows_k(const float* __restrict__ logits, const int* __restrict__ targets,
                            float* __restrict__ rowloss) {
    __shared__ float buf[256];
    const float* L = logits + (size_t)blockIdx.x * Vv;
    int tid = threadIdx.x;
    const int V4 = Vv / 4;
    float m = -INFINITY;
    for (int j = tid; j < V4; j += 256) {
        float4 v = ((const float4*)L)[j];
        m = fmaxf(m, fmaxf(fmaxf(v.x, v.y), fmaxf(v.z, v.w)));
    }
    m = block_reduce(m, buf, true);
    float s = 0.f;
    for (int j = tid; j < V4; j += 256) {
        float4 v = ((const float4*)L)[j];
        s += expf(v.x - m) + expf(v.y - m) + expf(v.z - m) + expf(v.w - m);
    }
    s = block_reduce(s, buf, false);
    if (tid == 0) rowloss[blockIdx.x] = logf(s) + m - L[targets[blockIdx.x]];
}

__global__ void loss_reduce_k(const float* __restrict__ rowloss, float* __restrict__ out) {
    __shared__ float buf[256];
    int tid = threadIdx.x;
    float s = 0.f;
    for (int j = tid; j < Mm; j += 256) s += rowloss[j];
    s = block_reduce(s, buf, false);
    if (tid == 0) out[0] = s / (float)Mm;
}

// ---------------- launch ----------------
extern "C" void kernel_launch(void* const* d_in, const int* in_sizes, int n_in,
                              void* d_out, int out_size)
{
    const int*   idx     = (const int*)d_in[0];
    const int*   targets = (const int*)d_in[1];
    const float* tok_emb = (const float*)d_in[2];
    const float* pos_emb = (const float*)d_in[3];
    const float* ln1_g   = (const float*)d_in[4];
    const float* ln1_b   = (const float*)d_in[5];
    const float* Wq      = (const float*)d_in[6];
    const float* Wk      = (const float*)d_in[7];
    const float* Wv      = (const float*)d_in[8];
    const float* Wo      = (const float*)d_in[9];
    const float* bo      = (const float*)d_in[10];
    const float* ln2_g   = (const float*)d_in[11];
    const float* ln2_b   = (const float*)d_in[12];
    const float* W1      = (const float*)d_in[13];
    const float* b1      = (const float*)d_in[14];
    const float* W2      = (const float*)d_in[15];
    const float* b2      = (const float*)d_in[16];
    const float* lnf_g   = (const float*)d_in[17];
    const float* lnf_b   = (const float*)d_in[18];
    const float* Wlm     = (const float*)d_in[19];
    const float* blm     = (const float*)d_in[20];
    float* out = (float*)d_out;

    float *px, *prl;
    bf16 *phhi, *phlo, *pqkvhi, *pqkvlo, *patthi, *pattlo, *pffhi, *pfflo, *pwhi, *pwlo;
    cudaGetSymbolAddress((void**)&px,     g_x);
    cudaGetSymbolAddress((void**)&prl,    g_rowloss);
    cudaGetSymbolAddress((void**)&phhi,   g_hhi);
    cudaGetSymbolAddress((void**)&phlo,   g_hlo);
    cudaGetSymbolAddress((void**)&pqkvhi, g_qkvhi);
    cudaGetSymbolAddress((void**)&pqkvlo, g_qkvlo);
    cudaGetSymbolAddress((void**)&patthi, g_atthi);
    cudaGetSymbolAddress((void**)&pattlo, g_attlo);
    cudaGetSymbolAddress((void**)&pffhi,  g_ffhhi);
    cudaGetSymbolAddress((void**)&pfflo,  g_ffhlo);
    cudaGetSymbolAddress((void**)&pwhi,   g_whi);
    cudaGetSymbolAddress((void**)&pwlo,   g_wlo);

    cudaFuncSetAttribute(gemm_tc<true,false,false,false>, cudaFuncAttributeMaxDynamicSharedMemorySize, GEMM_SMEM);
    cudaFuncSetAttribute(gemm_tc<false,true,true,false>,  cudaFuncAttributeMaxDynamicSharedMemorySize, GEMM_SMEM);
    cudaFuncSetAttribute(gemm_tc<true,true,false,true>,   cudaFuncAttributeMaxDynamicSharedMemorySize, GEMM_SMEM);
    cudaFuncSetAttribute(gemm_tc<false,true,false,false>, cudaFuncAttributeMaxDynamicSharedMemorySize, GEMM_SMEM);
    cudaFuncSetAttribute(flash_attn_k, cudaFuncAttributeMaxDynamicSharedMemorySize, FA_SMEM);

    embed_k<<<(Mm * Cc / 4 + 255) / 256, 256>>>(idx, tok_emb, pos_emb, px);

    dim3 gQKV(3072 / 128, Mm / 128);    // 24 x 32
    dim3 gC(Cc / 128, Mm / 128);        // 8 x 32
    dim3 gF(FFd / 128, Mm / 128);       // 32 x 32
    dim3 gVh(Vv / 128, Mm / 128);       // 393 x 32
    dim3 gFA(Tt / 64, Bb * Hh);         // 16 x 64

    for (int l = 0; l < Ll; ++l) {
        const size_t oCC = (size_t)l * Cc * Cc;
        const size_t oC  = (size_t)l * Cc;
        const size_t oCF = (size_t)l * Cc * FFd;
        const size_t oF  = (size_t)l * FFd;

        layernorm_split_k<<<Mm, 256>>>(px, ln1_g + oC, ln1_b + oC, phhi, phlo);
        conv_wqkv_k<<<dim3(Cc / 32, Cc / 32, 3), 256>>>(Wq + oCC, Wk + oCC, Wv + oCC,
                                                        pwhi, pwlo);
        gemm_tc<true,false,false,false><<<gQKV, 256, GEMM_SMEM>>>(
            Cc, phhi, phlo, pwhi, pwlo, nullptr, nullptr, 0,
            nullptr, pqkvhi, pqkvlo, 3072);

        flash_attn_k<<<gFA, 128, FA_SMEM>>>(pqkvhi, pqkvlo, patthi, pattlo);

        conv_wT_k<<<dim3(Cc / 32, Cc / 32), 256>>>(Wo + oCC, Cc, Cc, 0, pwhi, pwlo);
        gemm_tc<false,true,true,false><<<gC, 256, GEMM_SMEM>>>(
            Cc, patthi, pattlo, pwhi, pwlo, bo + oC, px, Cc,
            px, nullptr, nullptr, Cc);

        layernorm_split_k<<<Mm, 256>>>(px, ln2_g + oC, ln2_b + oC, phhi, phlo);
        conv_wT_k<<<dim3(FFd / 32, Cc / 32), 256>>>(W1 + oCF, Cc, FFd, 0, pwhi, pwlo);
        gemm_tc<true,true,false,true><<<gF, 256, GEMM_SMEM>>>(
            Cc, phhi, phlo, pwhi, pwlo, b1 + oF, nullptr, 0,
            nullptr, pffhi, pfflo, FFd);

        conv_wT_k<<<dim3(Cc / 32, FFd / 32), 256>>>(W2 + oCF, FFd, Cc, 0, pwhi, pwlo);
        gemm_tc<false,true,true,false><<<gC, 256, GEMM_SMEM>>>(
            FFd, pffhi, pfflo, pwhi, pwlo, b2 + oC, px, Cc,
            px, nullptr, nullptr, Cc);
    }

    // final LN + LM head -> logits into d_out
    layernorm_split_k<<<Mm, 256>>>(px, lnf_g, lnf_b, phhi, phlo);
    conv_wT_k<<<dim3(Vv / 32, Cc / 32), 256>>>(Wlm, Cc, Vv, 0, pwhi, pwlo);
    gemm_tc<false,true,false,false><<<gVh, 256, GEMM_SMEM>>>(
        Cc, phhi, phlo, pwhi, pwlo, blm, nullptr, 0,
        out, nullptr, nullptr, Vv);

    long long logitsN = (long long)Mm * Vv;
    if ((long long)out_size > logitsN) {
        loss_rows_k<<<Mm, 256>>>(out, targets, prl);
        loss_reduce_k<<<1, 256>>>(prl, out + logitsN);
    }
}

// round 11
// speedup vs baseline: 2.4573x; 1.1340x over previous
#include <cuda_runtime.h>
#include <cuda_bf16.h>
#include <math.h>
#include <stdint.h>

// Problem constants
#define Bb 4
#define Tt 1024
#define Cc 1024
#define Hh 16
#define HSs 64
#define Ll 12
#define Vv 50304
#define Mm (Bb*Tt)      // 4096
#define FFd (4*Cc)      // 4096

typedef __nv_bfloat16 bf16;

// ---------------- scratch (static device memory; no allocations) ----------------
__device__ float g_x[(size_t)Mm*Cc];
__device__ float g_rowloss[Mm];
__device__ bf16 g_hhi[(size_t)Mm*Cc];
__device__ bf16 g_hlo[(size_t)Mm*Cc];
__device__ bf16 g_qkvhi[(size_t)Mm*3072];
__device__ bf16 g_qkvlo[(size_t)Mm*3072];
__device__ bf16 g_atthi[(size_t)Mm*Cc];
__device__ bf16 g_attlo[(size_t)Mm*Cc];
__device__ bf16 g_ffhhi[(size_t)Mm*FFd];
__device__ bf16 g_ffhlo[(size_t)Mm*FFd];
__device__ bf16 g_whi[(size_t)Vv*Cc];
__device__ bf16 g_wlo[(size_t)Vv*Cc];

// ---------------- PTX helpers (portable, no arch-a gating) ----------------
__device__ __forceinline__ uint32_t smem_u32(const void* p) {
    uint32_t a;
    asm("{ .reg .u64 t; cvta.to.shared.u64 t, %1; cvt.u32.u64 %0, t; }" : "=r"(a) : "l"(p));
    return a;
}
__device__ __forceinline__ void ldsm4(uint32_t* r, uint32_t a) {
    asm volatile("ldmatrix.sync.aligned.m8n8.x4.shared.b16 {%0,%1,%2,%3}, [%4];"
        : "=r"(r[0]), "=r"(r[1]), "=r"(r[2]), "=r"(r[3]) : "r"(a));
}
__device__ __forceinline__ void ldsm4t(uint32_t* r, uint32_t a) {
    asm volatile("ldmatrix.sync.aligned.m8n8.x4.trans.shared.b16 {%0,%1,%2,%3}, [%4];"
        : "=r"(r[0]), "=r"(r[1]), "=r"(r[2]), "=r"(r[3]) : "r"(a));
}
__device__ __forceinline__ void mma16816(float* c, const uint32_t* a, uint32_t b0, uint32_t b1) {
    asm volatile("mma.sync.aligned.m16n8k16.row.col.f32.bf16.bf16.f32 "
        "{%0,%1,%2,%3}, {%4,%5,%6,%7}, {%8,%9}, {%0,%1,%2,%3};"
        : "+f"(c[0]), "+f"(c[1]), "+f"(c[2]), "+f"(c[3])
        : "r"(a[0]), "r"(a[1]), "r"(a[2]), "r"(a[3]), "r"(b0), "r"(b1));
}
__device__ __forceinline__ void cpa16(uint32_t saddr, const void* g) {
    asm volatile("cp.async.cg.shared.global [%0], [%1], 16;" :: "r"(saddr), "l"(g));
}
#define CPCOMMIT() asm volatile("cp.async.commit_group;" ::: "memory")
#define CPWAIT1()  asm volatile("cp.async.wait_group 1;" ::: "memory")
#define CPWAIT0()  asm volatile("cp.async.wait_group 0;" ::: "memory")

__device__ __forceinline__ float ex2f(float x) {
    float y; asm("ex2.approx.f32 %0, %1;" : "=f"(y) : "f"(x)); return y;
}
__device__ __forceinline__ void split2(float x, bf16& h, bf16& l) {
    h = __float2bfloat16(x);
    l = __float2bfloat16(x - __bfloat162float(h));
}
__device__ __forceinline__ uint32_t packbf(bf16 a, bf16 b) {
    return (uint32_t)__bfloat16_as_ushort(a) | ((uint32_t)__bfloat16_as_ushort(b) << 16);
}
__device__ __forceinline__ uint32_t splitpack(float x0, float x1, uint32_t& lo) {
    bf16 h0,l0,h1,l1;
    split2(x0,h0,l0); split2(x1,h1,l1);
    lo = packbf(l0,l1);
    return packbf(h0,h1);
}

// ---------------- helpers ----------------
__device__ __forceinline__ float block_reduce(float v, float* buf, bool ismax) {
    int tid = threadIdx.x;            // blockDim.x == 256
    buf[tid] = v;
    __syncthreads();
    #pragma unroll
    for (int s = 128; s > 0; s >>= 1) {
        if (tid < s) buf[tid] = ismax ? fmaxf(buf[tid], buf[tid + s]) : (buf[tid] + buf[tid + s]);
        __syncthreads();
    }
    float r = buf[0];
    __syncthreads();
    return r;
}

// ---------------- embed ----------------
__global__ void embed_k(const int* __restrict__ idx, const float* __restrict__ tok,
                        const float* __restrict__ pos, float* __restrict__ x) {
    int i4 = blockIdx.x * blockDim.x + threadIdx.x;
    if (i4 >= Mm * Cc / 4) return;
    int c  = (i4 % (Cc / 4)) * 4;
    int bt = i4 / (Cc / 4);
    int t  = bt % Tt;
    int tk = idx[bt];
    float4 a = *(const float4*)&tok[(size_t)tk * Cc + c];
    float4 p = *(const float4*)&pos[(size_t)t * Cc + c];
    a.x += p.x; a.y += p.y; a.z += p.z; a.w += p.w;
    *(float4*)&x[(size_t)bt * Cc + c] = a;
}

// ---------------- layernorm: fp32 in, bf16 hi/lo out ----------------
__global__ void layernorm_split_k(const float* __restrict__ x, const float* __restrict__ g,
                                  const float* __restrict__ b,
                                  bf16* __restrict__ yhi, bf16* __restrict__ ylo) {
    __shared__ float buf[256];
    int tid = threadIdx.x;
    const float* xr = x + (size_t)blockIdx.x * Cc;
    float4 v = ((const float4*)xr)[tid];
    float s  = v.x + v.y + v.z + v.w;
    float sq = v.x*v.x + v.y*v.y + v.z*v.z + v.w*v.w;
    s  = block_reduce(s,  buf, false);
    sq = block_reduce(sq, buf, false);
    float mean = s * (1.0f / Cc);
    float var  = sq * (1.0f / Cc) - mean * mean;
    float r    = rsqrtf(var + 1e-5f);
    float4 gg = ((const float4*)g)[tid];
    float4 bb = ((const float4*)b)[tid];
    float o0 = (v.x - mean) * r * gg.x + bb.x;
    float o1 = (v.y - mean) * r * gg.y + bb.y;
    float o2 = (v.z - mean) * r * gg.z + bb.z;
    float o3 = (v.w - mean) * r * gg.w + bb.w;
    uint2 wh, wl;
    wh.x = splitpack(o0, o1, wl.x);
    wh.y = splitpack(o2, o3, wl.y);
    ((uint2*)(yhi + (size_t)blockIdx.x * Cc))[tid] = wh;
    ((uint2*)(ylo + (size_t)blockIdx.x * Cc))[tid] = wl;
}

// ---------------- W [K,N] fp32 -> transposed [N,K] bf16 hi/lo at row offset ----------------
__global__ void conv_wT_k(const float* __restrict__ W, int K, int N, int n_off,
                          bf16* __restrict__ hi, bf16* __restrict__ lo) {
    __shared__ float t[32][33];
    int n0 = blockIdx.x * 32, k0 = blockIdx.y * 32;
    int tx = threadIdx.x & 31, ty = threadIdx.x >> 5;   // 256 threads: 32 x 8
    #pragma unroll
    for (int i = 0; i < 32; i += 8)
        t[ty + i][tx] = W[(size_t)(k0 + ty + i) * N + n0 + tx];
    __syncthreads();
    #pragma unroll
    for (int i = 0; i < 32; i += 8) {
        int n = ty + i;
        float x = t[tx][n];                          // W[k0+tx][n0+n]
        bf16 h, l;
        split2(x, h, l);
        hi[(size_t)(n_off + n0 + n) * K + k0 + tx] = h;
        lo[(size_t)(n_off + n0 + n) * K + k0 + tx] = l;
    }
}

// QKV weights: 3 convs in one launch (z selects the matrix)
__global__ void conv_wqkv_k(const float* __restrict__ Wq, const float* __restrict__ Wk,
                            const float* __restrict__ Wv,
                            bf16* __restrict__ hi, bf16* __restrict__ lo) {
    __shared__ float t[32][33];
    const float* W = (blockIdx.z == 0) ? Wq : (blockIdx.z == 1) ? Wk : Wv;
    int n_off = blockIdx.z * 1024;
    int n0 = blockIdx.x * 32, k0 = blockIdx.y * 32;
    int tx = threadIdx.x & 31, ty = threadIdx.x >> 5;
    #pragma unroll
    for (int i = 0; i < 32; i += 8)
        t[ty + i][tx] = W[(size_t)(k0 + ty + i) * Cc + n0 + tx];
    __syncthreads();
    #pragma unroll
    for (int i = 0; i < 32; i += 8) {
        int n = ty + i;
        float x = t[tx][n];
        bf16 h, l;
        split2(x, h, l);
        hi[(size_t)(n_off + n0 + n) * Cc + k0 + tx] = h;
        lo[(size_t)(n_off + n0 + n) * Cc + k0 + tx] = l;
    }
}

// ---------------- bf16x3 tensor-core GEMM, cp.async 2-stage pipeline, 2 CTAs/SM ----------------
#define BKh      32
#define ROWH     40
#define ARR_B    (128 * ROWH * 2)      // 10240 B
#define STAGE_B  (4 * ARR_B)           // 40960 B
#define GEMM_SMEM (2 * STAGE_B)        // 81920 B -> 2 CTAs per SM

__device__ __forceinline__ void issue_stage(
    uint32_t sbase, int buf, int tid, int rowBase, int colBase, int K, int k0,
    const bf16* __restrict__ Ahi, const bf16* __restrict__ Alo,
    const bf16* __restrict__ Bhi, const bf16* __restrict__ Blo)
{
    const int lrow = tid >> 2;
    const int lc8  = (tid & 3) << 3;
    uint32_t sb = sbase + (uint32_t)buf * STAGE_B;
    #pragma unroll
    for (int p = 0; p < 8; ++p) {
        int arr = p >> 1;
        int row = ((p & 1) << 6) + lrow;
        const bf16* src = (arr == 0) ? Ahi : (arr == 1) ? Alo : (arr == 2) ? Bhi : Blo;
        int rb = (arr < 2) ? rowBase : colBase;
        cpa16(sb + arr * ARR_B + (row * ROWH + lc8) * 2,
              src + (size_t)(rb + row) * K + k0 + lc8);
    }
}

template<bool SPLIT, bool BIAS, bool RES, bool RELU>
__global__ void __launch_bounds__(256, 2) gemm_tc(
    int K,
    const bf16* __restrict__ Ahi, const bf16* __restrict__ Alo,
    const bf16* __restrict__ Bhi, const bf16* __restrict__ Blo,
    const float* __restrict__ bias, const float* __restrict__ res, int ldr,
    float* __restrict__ C, bf16* __restrict__ Chi, bf16* __restrict__ Clo, int ldc)
{
    extern __shared__ __align__(16) char smem[];
    const uint32_t sbase = smem_u32(smem);
    const int tid  = threadIdx.x;
    const int lane = tid & 31;
    const int warp = tid >> 5;
    const int m0 = (warp & 1) * 64, n0 = (warp >> 1) * 32;
    const int rowBase = blockIdx.y * 128;
    const int colBase = blockIdx.x * 128;

    float acc[4][4][4];
    #pragma unroll
    for (int i = 0; i < 4; ++i)
        #pragma unroll
        for (int j = 0; j < 4; ++j)
            #pragma unroll
            for (int q = 0; q < 4; ++q) acc[i][j][q] = 0.f;

    const int NC = K / BKh;

    issue_stage(sbase, 0, tid, rowBase, colBase, K, 0, Ahi, Alo, Bhi, Blo);
    CPCOMMIT();

    const int lr16 = lane & 15;
    const int lk8  = (lane >> 4) << 3;

    for (int c = 0; c < NC; ++c) {
        if (c + 1 < NC) {
            // issue next chunk into the other buffer (its consumers finished
            // at the end-of-iteration __syncthreads of chunk c-1)
            issue_stage(sbase, (c + 1) & 1, tid, rowBase, colBase, K, (c + 1) * BKh,
                        Ahi, Alo, Bhi, Blo);
            CPCOMMIT();
            CPWAIT1();
        } else {
            CPWAIT0();
        }
        __syncthreads();
        const uint32_t st = sbase + (uint32_t)(c & 1) * STAGE_B;

        #pragma unroll
        for (int ks = 0; ks < 2; ++ks) {
            uint32_t bh[2][4], bl[2][4];
            #pragma unroll
            for (int np = 0; np < 2; ++np) {
                uint32_t off = ((n0 + np * 16 + lr16) * ROWH + ks * 16 + lk8) * 2;
                ldsm4(bh[np], st + 2 * ARR_B + off);
                ldsm4(bl[np], st + 3 * ARR_B + off);
            }
            uint32_t ah[4][4], av[4][4];
            #pragma unroll
            for (int mf = 0; mf < 4; ++mf) {
                uint32_t off = ((m0 + mf * 16 + lr16) * ROWH + ks * 16 + lk8) * 2;
                ldsm4(ah[mf], st + off);
                ldsm4(av[mf], st + ARR_B + off);
            }
            // term-major ordering: same-acc reuse distance = 16 MMAs
            #pragma unroll
            for (int mf = 0; mf < 4; ++mf)
                #pragma unroll
                for (int nf = 0; nf < 4; ++nf) {
                    int np = nf >> 1, sub = nf & 1;
                    mma16816(acc[mf][nf], ah[mf], bh[np][sub], bh[np][sub + 2]);
                }
            #pragma unroll
            for (int mf = 0; mf < 4; ++mf)
                #pragma unroll
                for (int nf = 0; nf < 4; ++nf) {
                    int np = nf >> 1, sub = nf & 1;
                    mma16816(acc[mf][nf], ah[mf], bl[np][sub], bl[np][sub + 2]);
                }
            #pragma unroll
            for (int mf = 0; mf < 4; ++mf)
                #pragma unroll
                for (int nf = 0; nf < 4; ++nf) {
                    int np = nf >> 1, sub = nf & 1;
                    mma16816(acc[mf][nf], av[mf], bh[np][sub], bh[np][sub + 2]);
                }
        }
        __syncthreads();
    }

    const int erow = lane >> 2;
    const int ecol = (lane & 3) << 1;
    #pragma unroll
    for (int mf = 0; mf < 4; ++mf) {
        #pragma unroll
        for (int nf = 0; nf < 4; ++nf) {
            int row = rowBase + m0 + mf * 16 + erow;
            int col = colBase + n0 + nf * 8 + ecol;
            #pragma unroll
            for (int half = 0; half < 2; ++half) {
                int r = row + half * 8;
                float ox = acc[mf][nf][half * 2 + 0];
                float oy = acc[mf][nf][half * 2 + 1];
                if (BIAS) {
                    float2 bv = *(const float2*)&bias[col];
                    ox += bv.x; oy += bv.y;
                }
                if (RES) {
                    float2 rv = *(const float2*)&res[(size_t)r * ldr + col];
                    ox += rv.x; oy += rv.y;
                }
                if (RELU) { ox = fmaxf(ox, 0.f); oy = fmaxf(oy, 0.f); }
                if (SPLIT) {
                    uint32_t wl;
                    uint32_t wh = splitpack(ox, oy, wl);
                    *(uint32_t*)&Chi[(size_t)r * ldc + col] = wh;
                    *(uint32_t*)&Clo[(size_t)r * ldc + col] = wl;
                } else {
                    float2 o; o.x = ox; o.y = oy;
                    *(float2*)&C[(size_t)r * ldc + col] = o;
                }
            }
        }
    }
}

// ---------------- fused flash attention (bf16x3 MMA, online softmax) ----------------
// grid (T/64, B*H), 128 threads (4 warps, 16 rows each). Q tile 64x64 resident;
// iterate K/V tiles of 64. P stays in registers (acc layout == A-frag layout).
#define AROWH 72
#define FA_Q0 0
#define FA_Q1 9216
#define FA_K0 18432
#define FA_K1 27648
#define FA_V0 36864
#define FA_V1 46080
#define FA_SMEM 55296

__global__ void __launch_bounds__(128, 3) flash_attn_k(
    const bf16* __restrict__ qkvhi, const bf16* __restrict__ qkvlo,
    bf16* __restrict__ atthi, bf16* __restrict__ attlo)
{
    extern __shared__ __align__(16) char fsm[];
    const uint32_t sb = smem_u32(fsm);
    const int tid = threadIdx.x, lane = tid & 31, warp = tid >> 5;
    const int bh = blockIdx.y;
    const int b = bh >> 4, h = bh & 15;
    const int row0 = blockIdx.x * 64;
    const size_t qbase = (size_t)b * Tt * 3072 + h * 64;
    const size_t kbase = qbase + 1024;
    const size_t vbase = qbase + 2048;

    // load Q tile (hi/lo) once
    #pragma unroll
    for (int p = 0; p < 4; ++p) {
        int idx = tid + p * 128;
        int r = idx >> 3, c8 = (idx & 7) * 8;
        *(uint4*)(fsm + FA_Q0 + (r * AROWH + c8) * 2) =
            *(const uint4*)(qkvhi + qbase + (size_t)(row0 + r) * 3072 + c8);
        *(uint4*)(fsm + FA_Q1 + (r * AROWH + c8) * 2) =
            *(const uint4*)(qkvlo + qbase + (size_t)(row0 + r) * 3072 + c8);
    }

    const int m0 = warp * 16;
    const int lr16 = lane & 15, lk8 = (lane >> 4) << 3;
    const int g = lane >> 2;
    const int ec = (lane & 3) << 1;
    const float SCL = 0.125f * 1.4426950408889634f;   // to log2 domain

    float m_[2] = { -INFINITY, -INFINITY };
    float l_[2] = { 0.f, 0.f };
    float oacc[8][4];
    #pragma unroll
    for (int i = 0; i < 8; ++i)
        #pragma unroll
        for (int q = 0; q < 4; ++q) oacc[i][q] = 0.f;

    for (int j0 = 0; j0 <= row0; j0 += 64) {
        __syncthreads();
        #pragma unroll
        for (int p = 0; p < 4; ++p) {
            int idx = tid + p * 128;
            int r = idx >> 3, c8 = (idx & 7) * 8;
            *(uint4*)(fsm + FA_K0 + (r * AROWH + c8) * 2) =
                *(const uint4*)(qkvhi + kbase + (size_t)(j0 + r) * 3072 + c8);
            *(uint4*)(fsm + FA_K1 + (r * AROWH + c8) * 2) =
                *(const uint4*)(qkvlo + kbase + (size_t)(j0 + r) * 3072 + c8);
            *(uint4*)(fsm + FA_V0 + (r * AROWH + c8) * 2) =
                *(const uint4*)(qkvhi + vbase + (size_t)(j0 + r) * 3072 + c8);
            *(uint4*)(fsm + FA_V1 + (r * AROWH + c8) * 2) =
                *(const uint4*)(qkvlo + vbase + (size_t)(j0 + r) * 3072 + c8);
        }
        __syncthreads();

        // S = Q K^T (3-term)
        float sacc[8][4];
        #pragma unroll
        for (int i = 0; i < 8; ++i)
            #pragma unroll
            for (int q = 0; q < 4; ++q) sacc[i][q] = 0.f;

        #pragma unroll
        for (int ks = 0; ks < 4; ++ks) {
            uint32_t ah[4], al[4];
            uint32_t aoff = ((m0 + lr16) * AROWH + ks * 16 + lk8) * 2;
            ldsm4(ah, sb + FA_Q0 + aoff);
            ldsm4(al, sb + FA_Q1 + aoff);
            uint32_t kh[4][4], kl[4][4];
            #pragma unroll
            for (int np = 0; np < 4; ++np) {
                uint32_t boff = ((np * 16 + lr16) * AROWH + ks * 16 + lk8) * 2;
                ldsm4(kh[np], sb + FA_K0 + boff);
                ldsm4(kl[np], sb + FA_K1 + boff);
            }
            #pragma unroll
            for (int nf = 0; nf < 8; ++nf) {
                int np = nf >> 1, sub = nf & 1;
                mma16816(sacc[nf], ah, kh[np][sub], kh[np][sub + 2]);
            }
            #pragma unroll
            for (int nf = 0; nf < 8; ++nf) {
                int np = nf >> 1, sub = nf & 1;
                mma16816(sacc[nf], ah, kl[np][sub], kl[np][sub + 2]);
            }
            #pragma unroll
            for (int nf = 0; nf < 8; ++nf) {
                int np = nf >> 1, sub = nf & 1;
                mma16816(sacc[nf], al, kh[np][sub], kh[np][sub + 2]);
            }
        }

        // scale, mask (diagonal tile), row max
        const bool diag = (j0 == row0);
        float mx0 = -INFINITY, mx1 = -INFINITY;
        #pragma unroll
        for (int nf = 0; nf < 8; ++nf) {
            #pragma unroll
            for (int q = 0; q < 4; ++q) {
                float vsc = sacc[nf][q] * SCL;
                if (diag) {
                    int cc = nf * 8 + ec + (q & 1);
                    int rr = m0 + g + ((q >> 1) << 3);
                    if (cc > rr) vsc = -INFINITY;
                }
                sacc[nf][q] = vsc;
                if (q < 2) mx0 = fmaxf(mx0, vsc); else mx1 = fmaxf(mx1, vsc);
            }
        }
        mx0 = fmaxf(mx0, __shfl_xor_sync(0xffffffffu, mx0, 1));
        mx0 = fmaxf(mx0, __shfl_xor_sync(0xffffffffu, mx0, 2));
        mx1 = fmaxf(mx1, __shfl_xor_sync(0xffffffffu, mx1, 1));
        mx1 = fmaxf(mx1, __shfl_xor_sync(0xffffffffu, mx1, 2));

        float mn0 = fmaxf(m_[0], mx0), mn1 = fmaxf(m_[1], mx1);
        float a0 = ex2f(m_[0] - mn0), a1 = ex2f(m_[1] - mn1);
        m_[0] = mn0; m_[1] = mn1;

        float s0 = 0.f, s1 = 0.f;
        #pragma unroll
        for (int nf = 0; nf < 8; ++nf) {
            float p0 = ex2f(sacc[nf][0] - mn0);
            float p1 = ex2f(sacc[nf][1] - mn0);
            float p2 = ex2f(sacc[nf][2] - mn1);
            float p3 = ex2f(sacc[nf][3] - mn1);
            sacc[nf][0] = p0; sacc[nf][1] = p1; sacc[nf][2] = p2; sacc[nf][3] = p3;
            s0 += p0 + p1; s1 += p2 + p3;
        }
        l_[0] = l_[0] * a0 + s0;
        l_[1] = l_[1] * a1 + s1;
        #pragma unroll
        for (int nf = 0; nf < 8; ++nf) {
            oacc[nf][0] *= a0; oacc[nf][1] *= a0;
            oacc[nf][2] *= a1; oacc[nf][3] *= a1;
        }

        // pack P into A-fragments (acc layout == A-frag layout)
        uint32_t pah[4][4], pal[4][4];
        #pragma unroll
        for (int kf = 0; kf < 4; ++kf) {
            pah[kf][0] = splitpack(sacc[2*kf][0],   sacc[2*kf][1],   pal[kf][0]);
            pah[kf][1] = splitpack(sacc[2*kf][2],   sacc[2*kf][3],   pal[kf][1]);
            pah[kf][2] = splitpack(sacc[2*kf+1][0], sacc[2*kf+1][1], pal[kf][2]);
            pah[kf][3] = splitpack(sacc[2*kf+1][2], sacc[2*kf+1][3], pal[kf][3]);
        }

        // O += P @ V (3-term)
        #pragma unroll
        for (int kf = 0; kf < 4; ++kf) {
            uint32_t vh[4][4], vl[4][4];
            #pragma unroll
            for (int np = 0; np < 4; ++np) {
                uint32_t boff = ((kf * 16 + lr16) * AROWH + np * 16 + lk8) * 2;
                ldsm4t(vh[np], sb + FA_V0 + boff);
                ldsm4t(vl[np], sb + FA_V1 + boff);
            }
            #pragma unroll
            for (int nf = 0; nf < 8; ++nf) {
                int np = nf >> 1, sub = nf & 1;
                mma16816(oacc[nf], pah[kf], vh[np][sub * 2], vh[np][sub * 2 + 1]);
            }
            #pragma unroll
            for (int nf = 0; nf < 8; ++nf) {
                int np = nf >> 1, sub = nf & 1;
                mma16816(oacc[nf], pah[kf], vl[np][sub * 2], vl[np][sub * 2 + 1]);
            }
            #pragma unroll
            for (int nf = 0; nf < 8; ++nf) {
                int np = nf >> 1, sub = nf & 1;
                mma16816(oacc[nf], pal[kf], vh[np][sub * 2], vh[np][sub * 2 + 1]);
            }
        }
    }

    // finalize: divide by row sums (reduced over the 4-lane quad), split, write
    float l0 = l_[0], l1 = l_[1];
    l0 += __shfl_xor_sync(0xffffffffu, l0, 1);
    l0 += __shfl_xor_sync(0xffffffffu, l0, 2);
    l1 += __shfl_xor_sync(0xffffffffu, l1, 1);
    l1 += __shfl_xor_sync(0xffffffffu, l1, 2);
    float inv0 = 1.0f / l0, inv1 = 1.0f / l1;

    #pragma unroll
    for (int nf = 0; nf < 8; ++nf) {
        int col = h * 64 + nf * 8 + ec;
        size_t r0 = (size_t)b * Tt + row0 + m0 + g;
        uint32_t wl;
        uint32_t wh = splitpack(oacc[nf][0] * inv0, oacc[nf][1] * inv0, wl);
        *(uint32_t*)&atthi[r0 * Cc + col] = wh;
        *(uint32_t*)&attlo[r0 * Cc + col] = wl;
        wh = splitpack(oacc[nf][2] * inv1, oacc[nf][3] * inv1, wl);
        *(uint32_t*)&atthi[(r0 + 8) * Cc + col] = wh;
        *(uint32_t*)&attlo[(r0 + 8) * Cc + col] = wl;
    }
}

// ---------------- loss ----------------
__global__ void loss_rows_k(const float* __restrict__ logits, const int* __restrict__ targets,
                            float* __restrict__ rowloss) {
    __shared__ float buf[256];
    const float* L = logits + (size_t)blockIdx.x * Vv;
    int tid = threadIdx.x;
    const int V4 = Vv / 4;
    float m = -INFINITY;
    for (int j = tid; j < V4; j += 256) {
        float4 v = ((const float4*)L)[j];
        m = fmaxf(m, fmaxf(fmaxf(v.x, v.y), fmaxf(v.z, v.w)));
    }
    m = block_reduce(m, buf, true);
    float s = 0.f;
    for (int j = tid; j < V4; j += 256) {
        float4 v = ((const float4*)L)[j];
        s += expf(v.x - m) + expf(v.y - m) + expf(v.z - m) + expf(v.w - m);
    }
    s = block_reduce(s, buf, false);
    if (tid == 0) rowloss[blockIdx.x] = logf(s) + m - L[targets[blockIdx.x]];
}

__global__ void loss_reduce_k(const float* __restrict__ rowloss, float* __restrict__ out) {
    __shared__ float buf[256];
    int tid = threadIdx.x;
    float s = 0.f;
    for (int j = tid; j < Mm; j += 256) s += rowloss[j];
    s = block_reduce(s, buf, false);
    if (tid == 0) out[0] = s / (float)Mm;
}

// ---------------- launch ----------------
extern "C" void kernel_launch(void* const* d_in, const int* in_sizes, int n_in,
                              void* d_out, int out_size)
{
    const int*   idx     = (const int*)d_in[0];
    const int*   targets = (const int*)d_in[1];
    const float* tok_emb = (const float*)d_in[2];
    const float* pos_emb = (const float*)d_in[3];
    const float* ln1_g   = (const float*)d_in[4];
    const float* ln1_b   = (const float*)d_in[5];
    const float* Wq      = (const float*)d_in[6];
    const float* Wk      = (const float*)d_in[7];
    const float* Wv      = (const float*)d_in[8];
    const float* Wo      = (const float*)d_in[9];
    const float* bo      = (const float*)d_in[10];
    const float* ln2_g   = (const float*)d_in[11];
    const float* ln2_b   = (const float*)d_in[12];
    const float* W1      = (const float*)d_in[13];
    const float* b1      = (const float*)d_in[14];
    const float* W2      = (const float*)d_in[15];
    const float* b2      = (const float*)d_in[16];
    const float* lnf_g   = (const float*)d_in[17];
    const float* lnf_b   = (const float*)d_in[18];
    const float* Wlm     = (const float*)d_in[19];
    const float* blm     = (const float*)d_in[20];
    float* out = (float*)d_out;

    float *px, *prl;
    bf16 *phhi, *phlo, *pqkvhi, *pqkvlo, *patthi, *pattlo, *pffhi, *pfflo, *pwhi, *pwlo;
    cudaGetSymbolAddress((void**)&px,     g_x);
    cudaGetSymbolAddress((void**)&prl,    g_rowloss);
    cudaGetSymbolAddress((void**)&phhi,   g_hhi);
    cudaGetSymbolAddress((void**)&phlo,   g_hlo);
    cudaGetSymbolAddress((void**)&pqkvhi, g_qkvhi);
    cudaGetSymbolAddress((void**)&pqkvlo, g_qkvlo);
    cudaGetSymbolAddress((void**)&patthi, g_atthi);
    cudaGetSymbolAddress((void**)&pattlo, g_attlo);
    cudaGetSymbolAddress((void**)&pffhi,  g_ffhhi);
    cudaGetSymbolAddress((void**)&pfflo,  g_ffhlo);
    cudaGetSymbolAddress((void**)&pwhi,   g_whi);
    cudaGetSymbolAddress((void**)&pwlo,   g_wlo);

    cudaFuncSetAttribute(gemm_tc<true,false,false,false>, cudaFuncAttributeMaxDynamicSharedMemorySize, GEMM_SMEM);
    cudaFuncSetAttribute(gemm_tc<false,true,true,false>,  cudaFuncAttributeMaxDynamicSharedMemorySize, GEMM_SMEM);
    cudaFuncSetAttribute(gemm_tc<true,true,false,true>,   cudaFuncAttributeMaxDynamicSharedMemorySize, GEMM_SMEM);
    cudaFuncSetAttribute(gemm_tc<false,true,false,false>, cudaFuncAttributeMaxDynamicSharedMemorySize, GEMM_SMEM);
    cudaFuncSetAttribute(flash_attn_k, cudaFuncAttributeMaxDynamicSharedMemorySize, FA_SMEM);

    embed_k<<<(Mm * Cc / 4 + 255) / 256, 256>>>(idx, tok_emb, pos_emb, px);

    dim3 gQKV(3072 / 128, Mm / 128);    // 24 x 32
    dim3 gC(Cc / 128, Mm / 128);        // 8 x 32
    dim3 gF(FFd / 128, Mm / 128);       // 32 x 32
    dim3 gVh(Vv / 128, Mm / 128);       // 393 x 32
    dim3 gFA(Tt / 64, Bb * Hh);         // 16 x 64

    for (int l = 0; l < Ll; ++l) {
        const size_t oCC = (size_t)l * Cc * Cc;
        const size_t oC  = (size_t)l * Cc;
        const size_t oCF = (size_t)l * Cc * FFd;
        const size_t oF  = (size_t)l * FFd;

        layernorm_split_k<<<Mm, 256>>>(px, ln1_g + oC, ln1_b + oC, phhi, phlo);
        conv_wqkv_k<<<dim3(Cc / 32, Cc / 32, 3), 256>>>(Wq + oCC, Wk + oCC, Wv + oCC,
                                                        pwhi, pwlo);
        gemm_tc<true,false,false,false><<<gQKV, 256, GEMM_SMEM>>>(
            Cc, phhi, phlo, pwhi, pwlo, nullptr, nullptr, 0,
            nullptr, pqkvhi, pqkvlo, 3072);

        flash_attn_k<<<gFA, 128, FA_SMEM>>>(pqkvhi, pqkvlo, patthi, pattlo);

        conv_wT_k<<<dim3(Cc / 32, Cc / 32), 256>>>(Wo + oCC, Cc, Cc, 0, pwhi, pwlo);
        gemm_tc<false,true,true,false><<<gC, 256, GEMM_SMEM>>>(
            Cc, patthi, pattlo, pwhi, pwlo, bo + oC, px, Cc,
            px, nullptr, nullptr, Cc);

        layernorm_split_k<<<Mm, 256>>>(px, ln2_g + oC, ln2_b + oC, phhi, phlo);
        conv_wT_k<<<dim3(FFd / 32, Cc / 32), 256>>>(W1 + oCF, Cc, FFd, 0, pwhi, pwlo);
        gemm_tc<true,true,false,true><<<gF, 256, GEMM_SMEM>>>(
            Cc, phhi, phlo, pwhi, pwlo, b1 + oF, nullptr, 0,
            nullptr, pffhi, pfflo, FFd);

        conv_wT_k<<<dim3(Cc / 32, FFd / 32), 256>>>(W2 + oCF, FFd, Cc, 0, pwhi, pwlo);
        gemm_tc<false,true,true,false><<<gC, 256, GEMM_SMEM>>>(
            FFd, pffhi, pfflo, pwhi, pwlo, b2 + oC, px, Cc,
            px, nullptr, nullptr, Cc);
    }

    // final LN + LM head -> logits into d_out
    layernorm_split_k<<<Mm, 256>>>(px, lnf_g, lnf_b, phhi, phlo);
    conv_wT_k<<<dim3(Vv / 32, Cc / 32), 256>>>(Wlm, Cc, Vv, 0, pwhi, pwlo);
    gemm_tc<false,true,false,false><<<gVh, 256, GEMM_SMEM>>>(
        Cc, phhi, phlo, pwhi, pwlo, blm, nullptr, 0,
        out, nullptr, nullptr, Vv);

    long long logitsN = (long long)Mm * Vv;
    if ((long long)out_size > logitsN) {
        loss_rows_k<<<Mm, 256>>>(out, targets, prl);
        loss_reduce_k<<<1, 256>>>(prl, out + logitsN);
    }
}

// round 12
// speedup vs baseline: 2.4940x; 1.0149x over previous
#include <cuda_runtime.h>
#include <cuda_bf16.h>
#include <math.h>
#include <stdint.h>

// Problem constants
#define Bb 4
#define Tt 1024
#define Cc 1024
#define Hh 16
#define HSs 64
#define Ll 12
#define Vv 50304
#define Mm (Bb*Tt)      // 4096
#define FFd (4*Cc)      // 4096

typedef __nv_bfloat16 bf16;

// ---------------- scratch (static device memory; no allocations) ----------------
__device__ float g_x[(size_t)Mm*Cc];
__device__ float g_rowloss[Mm];
__device__ bf16 g_hhi[(size_t)Mm*Cc];
__device__ bf16 g_hlo[(size_t)Mm*Cc];
__device__ bf16 g_qkvhi[(size_t)Mm*3072];
__device__ bf16 g_qkvlo[(size_t)Mm*3072];
__device__ bf16 g_atthi[(size_t)Mm*Cc];
__device__ bf16 g_attlo[(size_t)Mm*Cc];
__device__ bf16 g_ffhhi[(size_t)Mm*FFd];
__device__ bf16 g_ffhlo[(size_t)Mm*FFd];
__device__ bf16 g_whi[(size_t)Vv*Cc];
__device__ bf16 g_wlo[(size_t)Vv*Cc];

// ---------------- PTX helpers (portable, no arch-a gating) ----------------
__device__ __forceinline__ uint32_t smem_u32(const void* p) {
    uint32_t a;
    asm("{ .reg .u64 t; cvta.to.shared.u64 t, %1; cvt.u32.u64 %0, t; }" : "=r"(a) : "l"(p));
    return a;
}
__device__ __forceinline__ void ldsm4(uint32_t* r, uint32_t a) {
    asm volatile("ldmatrix.sync.aligned.m8n8.x4.shared.b16 {%0,%1,%2,%3}, [%4];"
        : "=r"(r[0]), "=r"(r[1]), "=r"(r[2]), "=r"(r[3]) : "r"(a));
}
__device__ __forceinline__ void ldsm4t(uint32_t* r, uint32_t a) {
    asm volatile("ldmatrix.sync.aligned.m8n8.x4.trans.shared.b16 {%0,%1,%2,%3}, [%4];"
        : "=r"(r[0]), "=r"(r[1]), "=r"(r[2]), "=r"(r[3]) : "r"(a));
}
__device__ __forceinline__ void mma16816(float* c, const uint32_t* a, uint32_t b0, uint32_t b1) {
    asm volatile("mma.sync.aligned.m16n8k16.row.col.f32.bf16.bf16.f32 "
        "{%0,%1,%2,%3}, {%4,%5,%6,%7}, {%8,%9}, {%0,%1,%2,%3};"
        : "+f"(c[0]), "+f"(c[1]), "+f"(c[2]), "+f"(c[3])
        : "r"(a[0]), "r"(a[1]), "r"(a[2]), "r"(a[3]), "r"(b0), "r"(b1));
}
__device__ __forceinline__ void cpa16(uint32_t saddr, const void* g) {
    asm volatile("cp.async.cg.shared.global [%0], [%1], 16;" :: "r"(saddr), "l"(g));
}
#define CPCOMMIT() asm volatile("cp.async.commit_group;" ::: "memory")
#define CPWAIT0()  asm volatile("cp.async.wait_group 0;" ::: "memory")

__device__ __forceinline__ float ex2f(float x) {
    float y; asm("ex2.approx.f32 %0, %1;" : "=f"(y) : "f"(x)); return y;
}
__device__ __forceinline__ void split2(float x, bf16& h, bf16& l) {
    h = __float2bfloat16(x);
    l = __float2bfloat16(x - __bfloat162float(h));
}
__device__ __forceinline__ uint32_t packbf(bf16 a, bf16 b) {
    return (uint32_t)__bfloat16_as_ushort(a) | ((uint32_t)__bfloat16_as_ushort(b) << 16);
}
__device__ __forceinline__ uint32_t splitpack(float x0, float x1, uint32_t& lo) {
    bf16 h0,l0,h1,l1;
    split2(x0,h0,l0); split2(x1,h1,l1);
    lo = packbf(l0,l1);
    return packbf(h0,h1);
}

// ---------------- helpers ----------------
__device__ __forceinline__ float block_reduce(float v, float* buf, bool ismax) {
    int tid = threadIdx.x;            // blockDim.x == 256
    buf[tid] = v;
    __syncthreads();
    #pragma unroll
    for (int s = 128; s > 0; s >>= 1) {
        if (tid < s) buf[tid] = ismax ? fmaxf(buf[tid], buf[tid + s]) : (buf[tid] + buf[tid + s]);
        __syncthreads();
    }
    float r = buf[0];
    __syncthreads();
    return r;
}

// ---------------- embed ----------------
__global__ void embed_k(const int* __restrict__ idx, const float* __restrict__ tok,
                        const float* __restrict__ pos, float* __restrict__ x) {
    int i4 = blockIdx.x * blockDim.x + threadIdx.x;
    if (i4 >= Mm * Cc / 4) return;
    int c  = (i4 % (Cc / 4)) * 4;
    int bt = i4 / (Cc / 4);
    int t  = bt % Tt;
    int tk = idx[bt];
    float4 a = *(const float4*)&tok[(size_t)tk * Cc + c];
    float4 p = *(const float4*)&pos[(size_t)t * Cc + c];
    a.x += p.x; a.y += p.y; a.z += p.z; a.w += p.w;
    *(float4*)&x[(size_t)bt * Cc + c] = a;
}

// ---------------- layernorm: fp32 in, bf16 hi/lo out ----------------
__global__ void layernorm_split_k(const float* __restrict__ x, const float* __restrict__ g,
                                  const float* __restrict__ b,
                                  bf16* __restrict__ yhi, bf16* __restrict__ ylo) {
    __shared__ float buf[256];
    int tid = threadIdx.x;
    const float* xr = x + (size_t)blockIdx.x * Cc;
    float4 v = ((const float4*)xr)[tid];
    float s  = v.x + v.y + v.z + v.w;
    float sq = v.x*v.x + v.y*v.y + v.z*v.z + v.w*v.w;
    s  = block_reduce(s,  buf, false);
    sq = block_reduce(sq, buf, false);
    float mean = s * (1.0f / Cc);
    float var  = sq * (1.0f / Cc) - mean * mean;
    float r    = rsqrtf(var + 1e-5f);
    float4 gg = ((const float4*)g)[tid];
    float4 bb = ((const float4*)b)[tid];
    float o0 = (v.x - mean) * r * gg.x + bb.x;
    float o1 = (v.y - mean) * r * gg.y + bb.y;
    float o2 = (v.z - mean) * r * gg.z + bb.z;
    float o3 = (v.w - mean) * r * gg.w + bb.w;
    uint2 wh, wl;
    wh.x = splitpack(o0, o1, wl.x);
    wh.y = splitpack(o2, o3, wl.y);
    ((uint2*)(yhi + (size_t)blockIdx.x * Cc))[tid] = wh;
    ((uint2*)(ylo + (size_t)blockIdx.x * Cc))[tid] = wl;
}

// ---------------- W [K,N] fp32 -> transposed [N,K] bf16 hi/lo at row offset ----------------
__global__ void conv_wT_k(const float* __restrict__ W, int K, int N, int n_off,
                          bf16* __restrict__ hi, bf16* __restrict__ lo) {
    __shared__ float t[32][33];
    int n0 = blockIdx.x * 32, k0 = blockIdx.y * 32;
    int tx = threadIdx.x & 31, ty = threadIdx.x >> 5;   // 256 threads: 32 x 8
    #pragma unroll
    for (int i = 0; i < 32; i += 8)
        t[ty + i][tx] = W[(size_t)(k0 + ty + i) * N + n0 + tx];
    __syncthreads();
    #pragma unroll
    for (int i = 0; i < 32; i += 8) {
        int n = ty + i;
        float x = t[tx][n];                          // W[k0+tx][n0+n]
        bf16 h, l;
        split2(x, h, l);
        hi[(size_t)(n_off + n0 + n) * K + k0 + tx] = h;
        lo[(size_t)(n_off + n0 + n) * K + k0 + tx] = l;
    }
}

// QKV weights: 3 convs in one launch (z selects the matrix)
__global__ void conv_wqkv_k(const float* __restrict__ Wq, const float* __restrict__ Wk,
                            const float* __restrict__ Wv,
                            bf16* __restrict__ hi, bf16* __restrict__ lo) {
    __shared__ float t[32][33];
    const float* W = (blockIdx.z == 0) ? Wq : (blockIdx.z == 1) ? Wk : Wv;
    int n_off = blockIdx.z * 1024;
    int n0 = blockIdx.x * 32, k0 = blockIdx.y * 32;
    int tx = threadIdx.x & 31, ty = threadIdx.x >> 5;
    #pragma unroll
    for (int i = 0; i < 32; i += 8)
        t[ty + i][tx] = W[(size_t)(k0 + ty + i) * Cc + n0 + tx];
    __syncthreads();
    #pragma unroll
    for (int i = 0; i < 32; i += 8) {
        int n = ty + i;
        float x = t[tx][n];
        bf16 h, l;
        split2(x, h, l);
        hi[(size_t)(n_off + n0 + n) * Cc + k0 + tx] = h;
        lo[(size_t)(n_off + n0 + n) * Cc + k0 + tx] = l;
    }
}

// ---------------- bf16x3 tensor-core GEMM, cp.async, 1 sync/chunk, 2 CTAs/SM ----------------
#define BKh      32
#define ROWH     40
#define ARR_B    (128 * ROWH * 2)      // 10240 B
#define STAGE_B  (4 * ARR_B)           // 40960 B
#define GEMM_SMEM (2 * STAGE_B)        // 81920 B -> 2 CTAs per SM

__device__ __forceinline__ void issue_stage(
    uint32_t sbase, int buf, int tid, int rowBase, int colBase, int K, int k0,
    const bf16* __restrict__ Ahi, const bf16* __restrict__ Alo,
    const bf16* __restrict__ Bhi, const bf16* __restrict__ Blo)
{
    const int lrow = tid >> 2;
    const int lc8  = (tid & 3) << 3;
    uint32_t sb = sbase + (uint32_t)buf * STAGE_B;
    #pragma unroll
    for (int p = 0; p < 8; ++p) {
        int arr = p >> 1;
        int row = ((p & 1) << 6) + lrow;
        const bf16* src = (arr == 0) ? Ahi : (arr == 1) ? Alo : (arr == 2) ? Bhi : Blo;
        int rb = (arr < 2) ? rowBase : colBase;
        cpa16(sb + arr * ARR_B + (row * ROWH + lc8) * 2,
              src + (size_t)(rb + row) * K + k0 + lc8);
    }
}

template<bool SPLIT, bool BIAS, bool RES, bool RELU>
__global__ void __launch_bounds__(256, 2) gemm_tc(
    int K,
    const bf16* __restrict__ Ahi, const bf16* __restrict__ Alo,
    const bf16* __restrict__ Bhi, const bf16* __restrict__ Blo,
    const float* __restrict__ bias, const float* __restrict__ res, int ldr,
    float* __restrict__ C, bf16* __restrict__ Chi, bf16* __restrict__ Clo, int ldc)
{
    extern __shared__ __align__(16) char smem[];
    const uint32_t sbase = smem_u32(smem);
    const int tid  = threadIdx.x;
    const int lane = tid & 31;
    const int warp = tid >> 5;
    const int m0 = (warp & 1) * 64, n0 = (warp >> 1) * 32;
    const int rowBase = blockIdx.y * 128;
    const int colBase = blockIdx.x * 128;

    float acc[4][4][4];
    #pragma unroll
    for (int i = 0; i < 4; ++i)
        #pragma unroll
        for (int j = 0; j < 4; ++j)
            #pragma unroll
            for (int q = 0; q < 4; ++q) acc[i][j][q] = 0.f;

    const int NC = K / BKh;

    issue_stage(sbase, 0, tid, rowBase, colBase, K, 0, Ahi, Alo, Bhi, Blo);
    CPCOMMIT();

    // hoisted ldmatrix offsets (byte offsets within a stage)
    const int lr16 = lane & 15;
    const int lk8  = (lane >> 4) << 3;
    uint32_t offB[2], offA[4];
    #pragma unroll
    for (int np = 0; np < 2; ++np)
        offB[np] = ((n0 + np * 16 + lr16) * ROWH + lk8) * 2;
    #pragma unroll
    for (int mf = 0; mf < 4; ++mf)
        offA[mf] = ((m0 + mf * 16 + lr16) * ROWH + lk8) * 2;

    for (int c = 0; c < NC; ++c) {
        CPWAIT0();                      // only chunk c outstanding here
        __syncthreads();                // single barrier per chunk
        if (c + 1 < NC) {
            // other buffer's last readers finished before the barrier above
            issue_stage(sbase, (c + 1) & 1, tid, rowBase, colBase, K, (c + 1) * BKh,
                        Ahi, Alo, Bhi, Blo);
            CPCOMMIT();
        }
        const uint32_t st = sbase + (uint32_t)(c & 1) * STAGE_B;

        #pragma unroll
        for (int ks = 0; ks < 2; ++ks) {
            const uint32_t kadd = st + ks * 32;   // ks*16 halves = 32 bytes
            uint32_t bh[2][4], bl[2][4];
            #pragma unroll
            for (int np = 0; np < 2; ++np) {
                ldsm4(bh[np], kadd + 2 * ARR_B + offB[np]);
                ldsm4(bl[np], kadd + 3 * ARR_B + offB[np]);
            }
            uint32_t ah[4][4], av[4][4];
            #pragma unroll
            for (int mf = 0; mf < 4; ++mf) {
                ldsm4(ah[mf], kadd + offA[mf]);
                ldsm4(av[mf], kadd + ARR_B + offA[mf]);
            }
            // term-major ordering: same-acc reuse distance = 16 MMAs
            #pragma unroll
            for (int mf = 0; mf < 4; ++mf)
                #pragma unroll
                for (int nf = 0; nf < 4; ++nf) {
                    int np = nf >> 1, sub = nf & 1;
                    mma16816(acc[mf][nf], ah[mf], bh[np][sub], bh[np][sub + 2]);
                }
            #pragma unroll
            for (int mf = 0; mf < 4; ++mf)
                #pragma unroll
                for (int nf = 0; nf < 4; ++nf) {
                    int np = nf >> 1, sub = nf & 1;
                    mma16816(acc[mf][nf], ah[mf], bl[np][sub], bl[np][sub + 2]);
                }
            #pragma unroll
            for (int mf = 0; mf < 4; ++mf)
                #pragma unroll
                for (int nf = 0; nf < 4; ++nf) {
                    int np = nf >> 1, sub = nf & 1;
                    mma16816(acc[mf][nf], av[mf], bh[np][sub], bh[np][sub + 2]);
                }
        }
    }

    const int erow = lane >> 2;
    const int ecol = (lane & 3) << 1;
    #pragma unroll
    for (int mf = 0; mf < 4; ++mf) {
        #pragma unroll
        for (int nf = 0; nf < 4; ++nf) {
            int row = rowBase + m0 + mf * 16 + erow;
            int col = colBase + n0 + nf * 8 + ecol;
            #pragma unroll
            for (int half = 0; half < 2; ++half) {
                int r = row + half * 8;
                float ox = acc[mf][nf][half * 2 + 0];
                float oy = acc[mf][nf][half * 2 + 1];
                if (BIAS) {
                    float2 bv = *(const float2*)&bias[col];
                    ox += bv.x; oy += bv.y;
                }
                if (RES) {
                    float2 rv = *(const float2*)&res[(size_t)r * ldr + col];
                    ox += rv.x; oy += rv.y;
                }
                if (RELU) { ox = fmaxf(ox, 0.f); oy = fmaxf(oy, 0.f); }
                if (SPLIT) {
                    uint32_t wl;
                    uint32_t wh = splitpack(ox, oy, wl);
                    *(uint32_t*)&Chi[(size_t)r * ldc + col] = wh;
                    *(uint32_t*)&Clo[(size_t)r * ldc + col] = wl;
                } else {
                    float2 o; o.x = ox; o.y = oy;
                    *(float2*)&C[(size_t)r * ldc + col] = o;
                }
            }
        }
    }
}

// ---------------- fused flash attention (bf16x3 MMA, online softmax) ----------------
// grid (T/64, B*H), 128 threads (4 warps, 16 rows each). Q tile 64x64 resident;
// iterate K/V tiles of 64. P stays in registers (acc layout == A-frag layout).
#define AROWH 72
#define FA_Q0 0
#define FA_Q1 9216
#define FA_K0 18432
#define FA_K1 27648
#define FA_V0 36864
#define FA_V1 46080
#define FA_SMEM 55296

__global__ void __launch_bounds__(128, 3) flash_attn_k(
    const bf16* __restrict__ qkvhi, const bf16* __restrict__ qkvlo,
    bf16* __restrict__ atthi, bf16* __restrict__ attlo)
{
    extern __shared__ __align__(16) char fsm[];
    const uint32_t sb = smem_u32(fsm);
    const int tid = threadIdx.x, lane = tid & 31, warp = tid >> 5;
    const int bh = blockIdx.y;
    const int b = bh >> 4, h = bh & 15;
    const int row0 = blockIdx.x * 64;
    const size_t qbase = (size_t)b * Tt * 3072 + h * 64;
    const size_t kbase = qbase + 1024;
    const size_t vbase = qbase + 2048;

    // load Q tile (hi/lo) once
    #pragma unroll
    for (int p = 0; p < 4; ++p) {
        int idx = tid + p * 128;
        int r = idx >> 3, c8 = (idx & 7) * 8;
        *(uint4*)(fsm + FA_Q0 + (r * AROWH + c8) * 2) =
            *(const uint4*)(qkvhi + qbase + (size_t)(row0 + r) * 3072 + c8);
        *(uint4*)(fsm + FA_Q1 + (r * AROWH + c8) * 2) =
            *(const uint4*)(qkvlo + qbase + (size_t)(row0 + r) * 3072 + c8);
    }

    const int m0 = warp * 16;
    const int lr16 = lane & 15, lk8 = (lane >> 4) << 3;
    const int g = lane >> 2;
    const int ec = (lane & 3) << 1;
    const float SCL = 0.125f * 1.4426950408889634f;   // to log2 domain

    float m_[2] = { -INFINITY, -INFINITY };
    float l_[2] = { 0.f, 0.f };
    float oacc[8][4];
    #pragma unroll
    for (int i = 0; i < 8; ++i)
        #pragma unroll
        for (int q = 0; q < 4; ++q) oacc[i][q] = 0.f;

    for (int j0 = 0; j0 <= row0; j0 += 64) {
        __syncthreads();
        #pragma unroll
        for (int p = 0; p < 4; ++p) {
            int idx = tid + p * 128;
            int r = idx >> 3, c8 = (idx & 7) * 8;
            *(uint4*)(fsm + FA_K0 + (r * AROWH + c8) * 2) =
                *(const uint4*)(qkvhi + kbase + (size_t)(j0 + r) * 3072 + c8);
            *(uint4*)(fsm + FA_K1 + (r * AROWH + c8) * 2) =
                *(const uint4*)(qkvlo + kbase + (size_t)(j0 + r) * 3072 + c8);
            *(uint4*)(fsm + FA_V0 + (r * AROWH + c8) * 2) =
                *(const uint4*)(qkvhi + vbase + (size_t)(j0 + r) * 3072 + c8);
            *(uint4*)(fsm + FA_V1 + (r * AROWH + c8) * 2) =
                *(const uint4*)(qkvlo + vbase + (size_t)(j0 + r) * 3072 + c8);
        }
        __syncthreads();

        // S = Q K^T (3-term)
        float sacc[8][4];
        #pragma unroll
        for (int i = 0; i < 8; ++i)
            #pragma unroll
            for (int q = 0; q < 4; ++q) sacc[i][q] = 0.f;

        #pragma unroll
        for (int ks = 0; ks < 4; ++ks) {
            uint32_t ah[4], al[4];
            uint32_t aoff = ((m0 + lr16) * AROWH + ks * 16 + lk8) * 2;
            ldsm4(ah, sb + FA_Q0 + aoff);
            ldsm4(al, sb + FA_Q1 + aoff);
            uint32_t kh[4][4], kl[4][4];
            #pragma unroll
            for (int np = 0; np < 4; ++np) {
                uint32_t boff = ((np * 16 + lr16) * AROWH + ks * 16 + lk8) * 2;
                ldsm4(kh[np], sb + FA_K0 + boff);
                ldsm4(kl[np], sb + FA_K1 + boff);
            }
            #pragma unroll
            for (int nf = 0; nf < 8; ++nf) {
                int np = nf >> 1, sub = nf & 1;
                mma16816(sacc[nf], ah, kh[np][sub], kh[np][sub + 2]);
            }
            #pragma unroll
            for (int nf = 0; nf < 8; ++nf) {
                int np = nf >> 1, sub = nf & 1;
                mma16816(sacc[nf], ah, kl[np][sub], kl[np][sub + 2]);
            }
            #pragma unroll
            for (int nf = 0; nf < 8; ++nf) {
                int np = nf >> 1, sub = nf & 1;
                mma16816(sacc[nf], al, kh[np][sub], kh[np][sub + 2]);
            }
        }

        // scale, mask (diagonal tile), row max
        const bool diag = (j0 == row0);
        float mx0 = -INFINITY, mx1 = -INFINITY;
        #pragma unroll
        for (int nf = 0; nf < 8; ++nf) {
            #pragma unroll
            for (int q = 0; q < 4; ++q) {
                float vsc = sacc[nf][q] * SCL;
                if (diag) {
                    int cc = nf * 8 + ec + (q & 1);
                    int rr = m0 + g + ((q >> 1) << 3);
                    if (cc > rr) vsc = -INFINITY;
                }
                sacc[nf][q] = vsc;
                if (q < 2) mx0 = fmaxf(mx0, vsc); else mx1 = fmaxf(mx1, vsc);
            }
        }
        mx0 = fmaxf(mx0, __shfl_xor_sync(0xffffffffu, mx0, 1));
        mx0 = fmaxf(mx0, __shfl_xor_sync(0xffffffffu, mx0, 2));
        mx1 = fmaxf(mx1, __shfl_xor_sync(0xffffffffu, mx1, 1));
        mx1 = fmaxf(mx1, __shfl_xor_sync(0xffffffffu, mx1, 2));

        float mn0 = fmaxf(m_[0], mx0), mn1 = fmaxf(m_[1], mx1);
        float a0 = ex2f(m_[0] - mn0), a1 = ex2f(m_[1] - mn1);
        m_[0] = mn0; m_[1] = mn1;

        float s0 = 0.f, s1 = 0.f;
        #pragma unroll
        for (int nf = 0; nf < 8; ++nf) {
            float p0 = ex2f(sacc[nf][0] - mn0);
            float p1 = ex2f(sacc[nf][1] - mn0);
            float p2 = ex2f(sacc[nf][2] - mn1);
            float p3 = ex2f(sacc[nf][3] - mn1);
            sacc[nf][0] = p0; sacc[nf][1] = p1; sacc[nf][2] = p2; sacc[nf][3] = p3;
            s0 += p0 + p1; s1 += p2 + p3;
        }
        l_[0] = l_[0] * a0 + s0;
        l_[1] = l_[1] * a1 + s1;
        #pragma unroll
        for (int nf = 0; nf < 8; ++nf) {
            oacc[nf][0] *= a0; oacc[nf][1] *= a0;
            oacc[nf][2] *= a1; oacc[nf][3] *= a1;
        }

        // pack P into A-fragments (acc layout == A-frag layout)
        uint32_t pah[4][4], pal[4][4];
        #pragma unroll
        for (int kf = 0; kf < 4; ++kf) {
            pah[kf][0] = splitpack(sacc[2*kf][0],   sacc[2*kf][1],   pal[kf][0]);
            pah[kf][1] = splitpack(sacc[2*kf][2],   sacc[2*kf][3],   pal[kf][1]);
            pah[kf][2] = splitpack(sacc[2*kf+1][0], sacc[2*kf+1][1], pal[kf][2]);
            pah[kf][3] = splitpack(sacc[2*kf+1][2], sacc[2*kf+1][3], pal[kf][3]);
        }

        // O += P @ V (3-term)
        #pragma unroll
        for (int kf = 0; kf < 4; ++kf) {
            uint32_t vh[4][4], vl[4][4];
            #pragma unroll
            for (int np = 0; np < 4; ++np) {
                uint32_t boff = ((kf * 16 + lr16) * AROWH + np * 16 + lk8) * 2;
                ldsm4t(vh[np], sb + FA_V0 + boff);
                ldsm4t(vl[np], sb + FA_V1 + boff);
            }
            #pragma unroll
            for (int nf = 0; nf < 8; ++nf) {
                int np = nf >> 1, sub = nf & 1;
                mma16816(oacc[nf], pah[kf], vh[np][sub * 2], vh[np][sub * 2 + 1]);
            }
            #pragma unroll
            for (int nf = 0; nf < 8; ++nf) {
                int np = nf >> 1, sub = nf & 1;
                mma16816(oacc[nf], pah[kf], vl[np][sub * 2], vl[np][sub * 2 + 1]);
            }
            #pragma unroll
            for (int nf = 0; nf < 8; ++nf) {
                int np = nf >> 1, sub = nf & 1;
                mma16816(oacc[nf], pal[kf], vh[np][sub * 2], vh[np][sub * 2 + 1]);
            }
        }
    }

    // finalize: divide by row sums (reduced over the 4-lane quad), split, write
    float l0 = l_[0], l1 = l_[1];
    l0 += __shfl_xor_sync(0xffffffffu, l0, 1);
    l0 += __shfl_xor_sync(0xffffffffu, l0, 2);
    l1 += __shfl_xor_sync(0xffffffffu, l1, 1);
    l1 += __shfl_xor_sync(0xffffffffu, l1, 2);
    float inv0 = 1.0f / l0, inv1 = 1.0f / l1;

    #pragma unroll
    for (int nf = 0; nf < 8; ++nf) {
        int col = h * 64 + nf * 8 + ec;
        size_t r0 = (size_t)b * Tt + row0 + m0 + g;
        uint32_t wl;
        uint32_t wh = splitpack(oacc[nf][0] * inv0, oacc[nf][1] * inv0, wl);
        *(uint32_t*)&atthi[r0 * Cc + col] = wh;
        *(uint32_t*)&attlo[r0 * Cc + col] = wl;
        wh = splitpack(oacc[nf][2] * inv1, oacc[nf][3] * inv1, wl);
        *(uint32_t*)&atthi[(r0 + 8) * Cc + col] = wh;
        *(uint32_t*)&attlo[(r0 + 8) * Cc + col] = wl;
    }
}

// ---------------- loss ----------------
__global__ void loss_rows_k(const float* __restrict__ logits, const int* __restrict__ targets,
                            float* __restrict__ rowloss) {
    __shared__ float buf[256];
    const float* L = logits + (size_t)blockIdx.x * Vv;
    int tid = threadIdx.x;
    const int V4 = Vv / 4;
    float m = -INFINITY;
    for (int j = tid; j < V4; j += 256) {
        float4 v = ((const float4*)L)[j];
        m = fmaxf(m, fmaxf(fmaxf(v.x, v.y), fmaxf(v.z, v.w)));
    }
    m = block_reduce(m, buf, true);
    float s = 0.f;
    for (int j = tid; j < V4; j += 256) {
        float4 v = ((const float4*)L)[j];
        s += expf(v.x - m) + expf(v.y - m) + expf(v.z - m) + expf(v.w - m);
    }
    s = block_reduce(s, buf, false);
    if (tid == 0) rowloss[blockIdx.x] = logf(s) + m - L[targets[blockIdx.x]];
}

__global__ void loss_reduce_k(const float* __restrict__ rowloss, float* __restrict__ out) {
    __shared__ float buf[256];
    int tid = threadIdx.x;
    float s = 0.f;
    for (int j = tid; j < Mm; j += 256) s += rowloss[j];
    s = block_reduce(s, buf, false);
    if (tid == 0) out[0] = s / (float)Mm;
}

// ---------------- launch ----------------
extern "C" void kernel_launch(void* const* d_in, const int* in_sizes, int n_in,
                              void* d_out, int out_size)
{
    const int*   idx     = (const int*)d_in[0];
    const int*   targets = (const int*)d_in[1];
    const float* tok_emb = (const float*)d_in[2];
    const float* pos_emb = (const float*)d_in[3];
    const float* ln1_g   = (const float*)d_in[4];
    const float* ln1_b   = (const float*)d_in[5];
    const float* Wq      = (const float*)d_in[6];
    const float* Wk      = (const float*)d_in[7];
    const float* Wv      = (const float*)d_in[8];
    const float* Wo      = (const float*)d_in[9];
    const float* bo      = (const float*)d_in[10];
    const float* ln2_g   = (const float*)d_in[11];
    const float* ln2_b   = (const float*)d_in[12];
    const float* W1      = (const float*)d_in[13];
    const float* b1      = (const float*)d_in[14];
    const float* W2      = (const float*)d_in[15];
    const float* b2      = (const float*)d_in[16];
    const float* lnf_g   = (const float*)d_in[17];
    const float* lnf_b   = (const float*)d_in[18];
    const float* Wlm     = (const float*)d_in[19];
    const float* blm     = (const float*)d_in[20];
    float* out = (float*)d_out;

    float *px, *prl;
    bf16 *phhi, *phlo, *pqkvhi, *pqkvlo, *patthi, *pattlo, *pffhi, *pfflo, *pwhi, *pwlo;
    cudaGetSymbolAddress((void**)&px,     g_x);
    cudaGetSymbolAddress((void**)&prl,    g_rowloss);
    cudaGetSymbolAddress((void**)&phhi,   g_hhi);
    cudaGetSymbolAddress((void**)&phlo,   g_hlo);
    cudaGetSymbolAddress((void**)&pqkvhi, g_qkvhi);
    cudaGetSymbolAddress((void**)&pqkvlo, g_qkvlo);
    cudaGetSymbolAddress((void**)&patthi, g_atthi);
    cudaGetSymbolAddress((void**)&pattlo, g_attlo);
    cudaGetSymbolAddress((void**)&pffhi,  g_ffhhi);
    cudaGetSymbolAddress((void**)&pfflo,  g_ffhlo);
    cudaGetSymbolAddress((void**)&pwhi,   g_whi);
    cudaGetSymbolAddress((void**)&pwlo,   g_wlo);

    cudaFuncSetAttribute(gemm_tc<true,false,false,false>, cudaFuncAttributeMaxDynamicSharedMemorySize, GEMM_SMEM);
    cudaFuncSetAttribute(gemm_tc<false,true,true,false>,  cudaFuncAttributeMaxDynamicSharedMemorySize, GEMM_SMEM);
    cudaFuncSetAttribute(gemm_tc<true,true,false,true>,   cudaFuncAttributeMaxDynamicSharedMemorySize, GEMM_SMEM);
    cudaFuncSetAttribute(gemm_tc<false,true,false,false>, cudaFuncAttributeMaxDynamicSharedMemorySize, GEMM_SMEM);
    cudaFuncSetAttribute(flash_attn_k, cudaFuncAttributeMaxDynamicSharedMemorySize, FA_SMEM);

    embed_k<<<(Mm * Cc / 4 + 255) / 256, 256>>>(idx, tok_emb, pos_emb, px);

    dim3 gQKV(3072 / 128, Mm / 128);    // 24 x 32
    dim3 gC(Cc / 128, Mm / 128);        // 8 x 32
    dim3 gF(FFd / 128, Mm / 128);       // 32 x 32
    dim3 gVh(Vv / 128, Mm / 128);       // 393 x 32
    dim3 gFA(Tt / 64, Bb * Hh);         // 16 x 64

    for (int l = 0; l < Ll; ++l) {
        const size_t oCC = (size_t)l * Cc * Cc;
        const size_t oC  = (size_t)l * Cc;
        const size_t oCF = (size_t)l * Cc * FFd;
        const size_t oF  = (size_t)l * FFd;

        layernorm_split_k<<<Mm, 256>>>(px, ln1_g + oC, ln1_b + oC, phhi, phlo);
        conv_wqkv_k<<<dim3(Cc / 32, Cc / 32, 3), 256>>>(Wq + oCC, Wk + oCC, Wv + oCC,
                                                        pwhi, pwlo);
        gemm_tc<true,false,false,false><<<gQKV, 256, GEMM_SMEM>>>(
            Cc, phhi, phlo, pwhi, pwlo, nullptr, nullptr, 0,
            nullptr, pqkvhi, pqkvlo, 3072);

        flash_attn_k<<<gFA, 128, FA_SMEM>>>(pqkvhi, pqkvlo, patthi, pattlo);

        conv_wT_k<<<dim3(Cc / 32, Cc / 32), 256>>>(Wo + oCC, Cc, Cc, 0, pwhi, pwlo);
        gemm_tc<false,true,true,false><<<gC, 256, GEMM_SMEM>>>(
            Cc, patthi, pattlo, pwhi, pwlo, bo + oC, px, Cc,
            px, nullptr, nullptr, Cc);

        layernorm_split_k<<<Mm, 256>>>(px, ln2_g + oC, ln2_b + oC, phhi, phlo);
        conv_wT_k<<<dim3(FFd / 32, Cc / 32), 256>>>(W1 + oCF, Cc, FFd, 0, pwhi, pwlo);
        gemm_tc<true,true,false,true><<<gF, 256, GEMM_SMEM>>>(
            Cc, phhi, phlo, pwhi, pwlo, b1 + oF, nullptr, 0,
            nullptr, pffhi, pfflo, FFd);

        conv_wT_k<<<dim3(Cc / 32, FFd / 32), 256>>>(W2 + oCF, FFd, Cc, 0, pwhi, pwlo);
        gemm_tc<false,true,true,false><<<gC, 256, GEMM_SMEM>>>(
            FFd, pffhi, pfflo, pwhi, pwlo, b2 + oC, px, Cc,
            px, nullptr, nullptr, Cc);
    }

    // final LN + LM head -> logits into d_out
    layernorm_split_k<<<Mm, 256>>>(px, lnf_g, lnf_b, phhi, phlo);
    conv_wT_k<<<dim3(Vv / 32, Cc / 32), 256>>>(Wlm, Cc, Vv, 0, pwhi, pwlo);
    gemm_tc<false,true,false,false><<<gVh, 256, GEMM_SMEM>>>(
        Cc, phhi, phlo, pwhi, pwlo, blm, nullptr, 0,
        out, nullptr, nullptr, Vv);

    long long logitsN = (long long)Mm * Vv;
    if ((long long)out_size > logitsN) {
        loss_rows_k<<<Mm, 256>>>(out, targets, prl);
        loss_reduce_k<<<1, 256>>>(prl, out + logitsN);
    }
}